// round 6
// baseline (speedup 1.0000x reference)
#include <cuda_runtime.h>
#include <math.h>
#include <stdint.h>

#define Bk   8
#define Nk   785
#define Ck   768
#define Hk   12
#define DHk  64
#define NTk  393
#define NM1  784
#define NTM1 392
#define FC   3072
#define SCALEF 0.125f
#define LNEPS 1e-5f
#define SMEPS 1e-6f
#define OUT_POL (Bk*NTk*Ck)
// eps/N computed in double then rounded to f32 (matches python 1e-6/785 -> f32)
#define EPSNF ((float)(1e-6/785.0))

// ------------------------- scratch (static device, no allocs) ----------------
__device__ __align__(16) float g_xn[Bk*Nk*Ck];
__device__ __align__(16) float g_q[Bk*Hk*Nk*DHk];
__device__ __align__(16) float g_k[Bk*Hk*Nk*DHk];
__device__ __align__(16) float g_v[Bk*Hk*Nk*DHk];
__device__ __align__(16) float g_attn0[Bk*Hk*Nk];
__device__ __align__(16) float g_vnorm[Bk*Nk];
__device__ __align__(16) int   g_order[Bk*NM1];
__device__ __align__(16) int   g_ui[Bk*NTM1];
__device__ __align__(16) float g_pol[Bk*NTk];
__device__ __align__(16) float g_attout[(size_t)Bk*NTk*Ck];
__device__ __align__(16) float g_ln2[(size_t)Bk*NTk*Ck];
__device__ __align__(16) float g_hbuf[(size_t)Bk*NTk*FC];

// ------------- LayerNorm, XLA:CPU-exact (sequential reduces, unfused) --------
__global__ __launch_bounds__(256) void ln_kernel(const float* __restrict__ in,
                                                 float* __restrict__ out,
                                                 const float* __restrict__ w,
                                                 const float* __restrict__ bb) {
    int r = blockIdx.x;
    int tid = threadIdx.x;
    __shared__ float row[Ck];
    __shared__ float s_mean, s_sd;
    const float* xr = in + (size_t)r * Ck;
    for (int e = tid; e < Ck; e += 256) row[e] = xr[e];
    __syncthreads();
    if (tid == 0) {
        float s = 0.f;
        for (int e = 0; e < Ck; e++) s = __fadd_rn(s, row[e]);
        float mean = __fdiv_rn(s, 768.0f);
        float v = 0.f;
        for (int e = 0; e < Ck; e++) {
            float d = __fsub_rn(row[e], mean);
            v = __fadd_rn(v, __fmul_rn(d, d));
        }
        float var = __fdiv_rn(v, 768.0f);
        s_mean = mean;
        s_sd = sqrtf(__fadd_rn(var, LNEPS));
    }
    __syncthreads();
    float mean = s_mean, sd = s_sd;
    for (int e = tid; e < Ck; e += 256)
        out[(size_t)r * Ck + e] =
            __fadd_rn(__fmul_rn(__fdiv_rn(__fsub_rn(row[e], mean), sd), w[e]), bb[e]);
}

// ------------------------- generic 64x64x16 fp32 GEMM ------------------------
// Accumulation: sequential over K ascending with FMA (matches Eigen gebp).
template <class Epi>
__global__ __launch_bounds__(256) void gemm64(const float* __restrict__ A,
                                              const float* __restrict__ Bm,
                                              int M, int Nn, int K, Epi epi) {
    __shared__ __align__(16) float As[16][68];
    __shared__ __align__(16) float Bs[16][64];
    int tid = threadIdx.x, tx = tid & 15, ty = tid >> 4;
    int row0 = blockIdx.y * 64, col0 = blockIdx.x * 64;
    float acc[4][4] = {};
    for (int k0 = 0; k0 < K; k0 += 16) {
#pragma unroll
        for (int l = 0; l < 4; l++) {
            int idx = tid + l * 256;
            int m = idx >> 4, kk = idx & 15;
            int r = row0 + m;
            As[kk][m] = (r < M) ? A[(size_t)r * K + k0 + kk] : 0.f;
        }
#pragma unroll
        for (int l = 0; l < 4; l++) {
            int idx = tid + l * 256;
            int kk = idx >> 6, n = idx & 63;
            Bs[kk][n] = Bm[(size_t)(k0 + kk) * Nn + col0 + n];
        }
        __syncthreads();
#pragma unroll
        for (int kk = 0; kk < 16; kk++) {
            float4 av = *(const float4*)&As[kk][ty * 4];
            float4 bv = *(const float4*)&Bs[kk][tx * 4];
            float a4[4] = {av.x, av.y, av.z, av.w};
            float b4[4] = {bv.x, bv.y, bv.z, bv.w};
#pragma unroll
            for (int i = 0; i < 4; i++)
#pragma unroll
                for (int j = 0; j < 4; j++)
                    acc[i][j] = fmaf(a4[i], b4[j], acc[i][j]);
        }
        __syncthreads();
    }
#pragma unroll
    for (int i = 0; i < 4; i++) {
        int r = row0 + ty * 4 + i;
        if (r >= M) continue;
#pragma unroll
        for (int j = 0; j < 4; j++) epi.op(r, col0 + tx * 4 + j, acc[i][j]);
    }
}

// ------------------------- epilogues ----------------------------------------
struct EpiQKV {
    const float* policy;
    __device__ void op(int i, int j, float acc) const {
        int b = i / Nk, n = i - b * Nk;
        float val = __fmul_rn(acc, policy[i]);
        int s = j / Ck, rem = j - s * Ck;
        int h = rem >> 6, d = rem & 63;
        size_t o = (((size_t)(b * Hk + h)) * Nk + n) * DHk + d;
        if (s == 0) g_q[o] = val; else if (s == 1) g_k[o] = val; else g_v[o] = val;
    }
};
struct EpiProj {
    const float* x; const float* pb; float* out;
    __device__ void op(int i, int j, float acc) const {
        int b = i / NTk, t = i - b * NTk;
        float val = (acc + pb[j]) * g_pol[i];
        float sx;
        if (t == 0) sx = x[((size_t)b * Nk) * Ck + j];
        else {
            int u = g_ui[b * NTM1 + t - 1];
            sx = (u == NM1) ? 0.f : x[((size_t)b * Nk + g_order[b * NM1 + u] + 1) * Ck + j];
        }
        out[(size_t)i * Ck + j] = sx + val;
    }
};
struct EpiFc1 {
    const float* fb;
    __device__ void op(int i, int j, float acc) const {
        float v = acc + fb[j];
        g_hbuf[(size_t)i * FC + j] = 0.5f * v * (1.0f + erff(v * 0.70710678118654752f));
    }
};
struct EpiFc2 {
    const float* fb; float* out;
    __device__ void op(int i, int j, float acc) const {
        out[(size_t)i * Ck + j] += (acc + fb[j]) * g_pol[i];
    }
};

// --------- attention row 0, XLA:CPU-exact (seq sum, correctly-rounded exp) ---
__global__ __launch_bounds__(256) void attn_row0_kernel() {
    int bh = blockIdx.x;          // b*12+h
    int tid = threadIdx.x;
    __shared__ float qs[64];
    __shared__ float lg[Nk];
    __shared__ float red[256];
    __shared__ float s_sum;
    const float* q0 = g_q + (size_t)bh * Nk * DHk;
    if (tid < 64) qs[tid] = q0[tid];
    __syncthreads();
    float lmax = -INFINITY;
    for (int m = tid; m < Nk; m += 256) {
        const float* kr = g_k + ((size_t)bh * Nk + m) * DHk;
        float d = 0.f;
#pragma unroll
        for (int e = 0; e < 64; e++) d = fmaf(qs[e], kr[e], d);
        d = __fmul_rn(d, SCALEF);
        lg[m] = d;
        lmax = fmaxf(lmax, d);
    }
    red[tid] = lmax; __syncthreads();
    // max is order-invariant (exact): tree OK
    for (int o = 128; o > 0; o >>= 1) { if (tid < o) red[tid] = fmaxf(red[tid], red[tid + o]); __syncthreads(); }
    float M = red[0]; __syncthreads();
    // correctly-rounded exp via double (matches host libm expf)
    for (int m = tid; m < Nk; m += 256)
        lg[m] = (float)exp((double)__fsub_rn(lg[m], M));
    __syncthreads();
    if (tid == 0) {
        float s = 0.f;
        for (int m = 0; m < Nk; m++) s = __fadd_rn(s, lg[m]);
        s_sum = s;
    }
    __syncthreads();
    float S = s_sum;
    for (int m = tid; m < Nk; m += 256)
        g_attn0[bh * Nk + m] = __fdiv_rn(__fadd_rn(lg[m], EPSNF), __fadd_rn(S, SMEPS));
}

// ---------------- v_norm: sequential sum of unfused squares ------------------
__global__ __launch_bounds__(256) void vnorm_kernel() {
    int i = blockIdx.x * 256 + threadIdx.x;
    if (i >= Bk * Nk) return;
    int b = i / Nk, n = i - b * Nk;
    float s = 0.f;
    for (int e = 0; e < Ck; e++) {
        int h = e >> 6, d = e & 63;
        float vv = g_v[(((size_t)(b * Hk + h)) * Nk + n) * DHk + d];
        s = __fadd_rn(s, __fmul_rn(vv, vv));
    }
    g_vnorm[i] = sqrtf(s);
}

// ------------------------- selection chain (one block per batch) -------------
__global__ __launch_bounds__(1024) void select_kernel(float* __restrict__ out) {
    int b = blockIdx.x, tid = threadIdx.x;
    __shared__ __align__(16) float sv[1024];
    __shared__ __align__(16) int   si[1024];
    __shared__ __align__(16) float lev[1024];
    __shared__ float s_total, s_cmin, s_cmax, s_ystart;
    __shared__ int   counts[Nk];

    // sig (sequential head sum, unfused mul by vnorm)
    if (tid < NM1) {
        int n = tid + 1;
        float s = 0.f;
        for (int h = 0; h < Hk; h++) s = __fadd_rn(s, g_attn0[(b * Hk + h) * Nk + n]);
        sv[tid] = __fmul_rn(s, g_vnorm[b * Nk + n]);
        si[tid] = tid;
    } else { sv[tid] = INFINITY; si[tid] = 1 << 30; }
    __syncthreads();
    if (tid == 0) {
        float s = 0.f;
        for (int j = 0; j < NM1; j++) s = __fadd_rn(s, sv[j]);
        s_total = s;
    }
    __syncthreads();
    if (tid < NM1) sv[tid] = __fdiv_rn(sv[tid], s_total);
    __syncthreads();

    // stable bitonic sort ascending by (value, index)
    for (int k = 2; k <= 1024; k <<= 1) {
        for (int j = k >> 1; j > 0; j >>= 1) {
            int ixj = tid ^ j;
            if (ixj > tid) {
                bool up = ((tid & k) == 0);
                float v1 = sv[tid], v2 = sv[ixj];
                int   i1 = si[tid], i2 = si[ixj];
                bool lt = (v1 < v2) || (v1 == v2 && i1 < i2);
                if (lt != up) { sv[tid] = v2; sv[ixj] = v1; si[tid] = i2; si[ixj] = i1; }
            }
            __syncthreads();
        }
    }
    if (tid < NM1) g_order[b * NM1 + tid] = si[tid];
    __syncthreads();

    // cumsum: exact replication of jax associative_scan (odd/even tree)
    {
        const int nlv[10] = {784, 392, 196, 98, 49, 24, 12, 6, 3, 1};
        const int off[10] = {0,   0,   392, 592, 692, 744, 768, 780, 788, 792};
        for (int j = 1; j <= 9; j++) {
            volatile const float* par = (j == 1) ? (volatile const float*)sv
                                                 : (volatile const float*)(lev + off[j - 1]);
            float* ch = lev + off[j];
            for (int i = tid; i < nlv[j]; i += 1024) {
                float a = par[2 * i];
                float c = par[2 * i + 1];
                ch[i] = __fadd_rn(a, c);
            }
            __syncthreads();
        }
        for (int j = 8; j >= 0; j--) {
            float* par = (j == 0) ? sv : (lev + off[j]);
            volatile const float* ch = (volatile const float*)(lev + off[j + 1]);
            for (int idx = tid; idx < nlv[j]; idx += 1024) {
                int kk = (idx & 1) ? (idx >> 1) : ((idx >> 1) - 1);
                float chv = (idx == 0) ? 0.f : ch[kk];
                float pv  = par[idx];
                float val;
                if (idx == 0)      val = pv;
                else if (idx & 1)  val = chv;
                else               val = __fadd_rn(chv, pv);
                par[idx] = val;
            }
            __syncthreads();
        }
    }
    // min/max over cdf (order-invariant, exact)
    if (tid == 0) {
        float mn = 1e30f, mx = -1e30f;
        for (int j = 0; j < NM1; j++) { mn = fminf(mn, sv[j]); mx = fmaxf(mx, sv[j]); }
        s_cmin = mn; s_cmax = mx;
    }
    __syncthreads();
    if (tid < NM1) sv[tid] = __fdiv_rn(__fsub_rn(sv[tid], s_cmin), __fsub_rn(s_cmax, s_cmin));
    __syncthreads();

    // ys_start = min(ncdf + (ncdf==0)*1e8)
    lev[tid] = (tid < NM1) ? __fadd_rn(sv[tid], ((sv[tid] == 0.f) ? 1e8f : 0.f)) : 1e30f;
    __syncthreads();
    for (int o = 512; o > 0; o >>= 1) { if (tid < o) lev[tid] = fminf(lev[tid], lev[tid + o]); __syncthreads(); }
    if (tid == 0) s_ystart = lev[0];
    __syncthreads();
    float ystart = s_ystart;

    // tokens_to_pick: argmin |ys - ncdf| (first occurrence); unfused ys math
    int tok = 0;
    if (tid < NM1) {
        const float delta = 1.0f / 783.0f;
        float tidf = (float)tid;
        float yl = (tid == 783) ? 1.0f : __fmul_rn(tidf, delta);
        float t1 = __fmul_rn(yl, 783.0f);
        float t2 = __fmul_rn(ystart, tidf);
        float ys = __fadd_rn(ystart, __fdiv_rn(__fsub_rn(t1, t2), 783.0f));
        float best = 1e30f; int bi = 0;
        for (int m = 0; m < NM1; m++) {
            float dd = fabsf(__fsub_rn(ys, sv[m]));
            if (dd < best) { best = dd; bi = m; }
        }
        tok = bi;
    }
    __syncthreads();

    // unique via counting (matches sort/mark/sort semantics)
    for (int c = tid; c < Nk; c += 1024) counts[c] = 0;
    __syncthreads();
    if (tid < NM1) atomicAdd(&counts[tok], 1);
    __syncthreads();
    if (tid == 0) {
        int pos = 0;
        for (int v = 0; v < NM1; v++) {
            if (counts[v] > 0) { if (pos < NTM1) g_ui[b * NTM1 + pos] = v; pos++; }
            if (pos >= NTM1) break;
        }
        for (; pos < NTM1; pos++) g_ui[b * NTM1 + pos] = NM1;
        g_pol[b * NTk] = 1.f;
        out[OUT_POL + b * NTk] = 1.f;
        for (int k = 0; k < NTM1; k++) {
            float pv = (g_ui[b * NTM1 + k] != NM1) ? 1.f : 0.f;
            g_pol[b * NTk + 1 + k] = pv;
            out[OUT_POL + b * NTk + 1 + k] = pv;
        }
    }
}

// --------- fused attention for the 393 selected rows (continuous path) -------
__global__ __launch_bounds__(256) void attnout_kernel() {
    int tc = blockIdx.x;     // chunk of 8 selected rows
    int h  = blockIdx.y;
    int b  = blockIdx.z;
    int tid = threadIdx.x;
    __shared__ float qs[8][64];
    __shared__ float pr[8][Nk];
    __shared__ int   rown[8];
    __shared__ float red[256];
    __shared__ float red2[4][512];

    if (tid < 8) {
        int t = tc * 8 + tid;
        int r = -2;
        if (t < NTk) {
            if (t == 0) r = 0;
            else {
                int u = g_ui[b * NTM1 + t - 1];
                r = (u == NM1) ? -1 : (g_order[b * NM1 + u] + 1);
            }
        }
        rown[tid] = r;
    }
    __syncthreads();
    for (int idx = tid; idx < 8 * 64; idx += 256) {
        int rr = idx >> 6, d = idx & 63;
        int r = rown[rr];
        qs[rr][d] = (r >= 0) ? g_q[(((size_t)(b * Hk + h)) * Nk + r) * DHk + d] : 0.f;
    }
    __syncthreads();

    for (int m = tid; m < Nk; m += 256) {
        const float* kr = g_k + (((size_t)(b * Hk + h)) * Nk + m) * DHk;
        float lacc[8] = {0, 0, 0, 0, 0, 0, 0, 0};
#pragma unroll
        for (int e = 0; e < 64; e++) {
            float kv = kr[e];
#pragma unroll
            for (int rr = 0; rr < 8; rr++) lacc[rr] = fmaf(qs[rr][e], kv, lacc[rr]);
        }
#pragma unroll
        for (int rr = 0; rr < 8; rr++) pr[rr][m] = lacc[rr] * SCALEF;
    }
    __syncthreads();

    for (int rr = 0; rr < 8; rr++) {
        int r = rown[rr];
        if (r < 0) {
            for (int m = tid; m < Nk; m += 256) pr[rr][m] = 0.f;
            __syncthreads();
            continue;
        }
        float lm = -1e30f;
        for (int m = tid; m < Nk; m += 256) lm = fmaxf(lm, pr[rr][m]);
        red[tid] = lm; __syncthreads();
        for (int o = 128; o > 0; o >>= 1) { if (tid < o) red[tid] = fmaxf(red[tid], red[tid + o]); __syncthreads(); }
        float M = red[0]; __syncthreads();
        float s = 0.f;
        for (int m = tid; m < Nk; m += 256) {
            float e = expf(pr[rr][m] - M);
            pr[rr][m] = e;
            s += e;
        }
        red[tid] = s; __syncthreads();
        for (int o = 128; o > 0; o >>= 1) { if (tid < o) red[tid] += red[tid + o]; __syncthreads(); }
        float S = red[0]; __syncthreads();
        for (int m = tid; m < Nk; m += 256) pr[rr][m] = (pr[rr][m] + EPSNF) / (S + SMEPS);
        __syncthreads();
    }

    int d = tid & 63, grp = tid >> 6;
    float acc[8] = {0, 0, 0, 0, 0, 0, 0, 0};
    for (int m = grp; m < Nk; m += 4) {
        float vv = g_v[(((size_t)(b * Hk + h)) * Nk + m) * DHk + d];
#pragma unroll
        for (int rr = 0; rr < 8; rr++) acc[rr] = fmaf(pr[rr][m], vv, acc[rr]);
    }
#pragma unroll
    for (int rr = 0; rr < 8; rr++) red2[grp][rr * 64 + d] = acc[rr];
    __syncthreads();
    for (int idx = tid; idx < 512; idx += 256) {
        int rr = idx >> 6, dd = idx & 63;
        int t = tc * 8 + rr;
        if (t < NTk) {
            float s = red2[0][idx] + red2[1][idx] + red2[2][idx] + red2[3][idx];
            g_attout[((size_t)(b * NTk + t)) * Ck + h * 64 + dd] = s;
        }
    }
}

// ------------------------- host orchestration --------------------------------
extern "C" void kernel_launch(void* const* d_in, const int* in_sizes, int n_in,
                              void* d_out, int out_size) {
    const float* x      = (const float*)d_in[0];
    const float* policy = (const float*)d_in[1];
    const float* n1w    = (const float*)d_in[2];
    const float* n1b    = (const float*)d_in[3];
    const float* qkvw   = (const float*)d_in[4];
    const float* projw  = (const float*)d_in[5];
    const float* projb  = (const float*)d_in[6];
    const float* n2w    = (const float*)d_in[7];
    const float* n2b    = (const float*)d_in[8];
    const float* fc1w   = (const float*)d_in[9];
    const float* fc1b   = (const float*)d_in[10];
    const float* fc2w   = (const float*)d_in[11];
    const float* fc2b   = (const float*)d_in[12];
    float* out = (float*)d_out;

    float *p_xn, *p_attout, *p_ln2, *p_h;
    cudaGetSymbolAddress((void**)&p_xn, g_xn);
    cudaGetSymbolAddress((void**)&p_attout, g_attout);
    cudaGetSymbolAddress((void**)&p_ln2, g_ln2);
    cudaGetSymbolAddress((void**)&p_h, g_hbuf);

    const int Mqkv = Bk * Nk;   // 6280
    const int Mt   = Bk * NTk;  // 3144

    ln_kernel<<<Mqkv, 256>>>(x, p_xn, n1w, n1b);

    {
        EpiQKV epi{policy};
        dim3 grid((3 * Ck) / 64, (Mqkv + 63) / 64);
        gemm64<EpiQKV><<<grid, 256>>>(p_xn, qkvw, Mqkv, 3 * Ck, Ck, epi);
    }

    attn_row0_kernel<<<Bk * Hk, 256>>>();
    vnorm_kernel<<<(Bk * Nk + 255) / 256, 256>>>();

    select_kernel<<<Bk, 1024>>>(out);

    {
        dim3 grid((NTk + 7) / 8, Hk, Bk);
        attnout_kernel<<<grid, 256>>>();
    }

    {
        EpiProj epi{x, projb, out};
        dim3 grid(Ck / 64, (Mt + 63) / 64);
        gemm64<EpiProj><<<grid, 256>>>(p_attout, projw, Mt, Ck, Ck, epi);
    }

    ln_kernel<<<Mt, 256>>>(out, p_ln2, n2w, n2b);

    {
        EpiFc1 epi{fc1b};
        dim3 grid(FC / 64, (Mt + 63) / 64);
        gemm64<EpiFc1><<<grid, 256>>>(p_ln2, fc1w, Mt, FC, Ck, epi);
    }

    {
        EpiFc2 epi{fc2b, out};
        dim3 grid(Ck / 64, (Mt + 63) / 64);
        gemm64<EpiFc2><<<grid, 256>>>(p_h, fc2w, Mt, Ck, FC, epi);
    }
    (void)in_sizes; (void)n_in; (void)out_size;
}

// round 7
// speedup vs baseline: 1.0573x; 1.0573x over previous
#include <cuda_runtime.h>
#include <math.h>
#include <stdint.h>

#define Bk   8
#define Nk   785
#define Ck   768
#define Hk   12
#define DHk  64
#define NTk  393
#define NM1  784
#define NTM1 392
#define FC   3072
#define SCALEF 0.125f
#define LNEPS 1e-5f
#define SMEPS 1e-6f
#define OUT_POL (Bk*NTk*Ck)
#define EPSNF ((float)(1e-6/785.0))

// ------------------------- scratch (static device, no allocs) ----------------
__device__ __align__(16) float g_xn[Bk*Nk*Ck];
__device__ __align__(16) float g_q[Bk*Hk*Nk*DHk];
__device__ __align__(16) float g_k[Bk*Hk*Nk*DHk];
__device__ __align__(16) float g_v[Bk*Hk*Nk*DHk];
__device__ __align__(16) float g_attn0[Bk*Hk*Nk];
__device__ __align__(16) float g_vnorm[Bk*Nk];
__device__ __align__(16) int   g_order[Bk*NM1];
__device__ __align__(16) int   g_ui[Bk*NTM1];
__device__ __align__(16) float g_pol[Bk*NTk];
__device__ __align__(16) float g_attout[(size_t)Bk*NTk*Ck];
__device__ __align__(16) float g_ln2[(size_t)Bk*NTk*Ck];
__device__ __align__(16) float g_hbuf[(size_t)Bk*NTk*FC];

// ------------- LayerNorm, XLA-exact, 8 rows/block (coalesced staging) --------
__global__ __launch_bounds__(256) void ln8_kernel(const float* __restrict__ in,
                                                  float* __restrict__ out,
                                                  const float* __restrict__ w,
                                                  const float* __restrict__ bb,
                                                  int M) {
    int r0 = blockIdx.x * 8;
    int tid = threadIdx.x;
    __shared__ __align__(16) float rows[8][772];   // pad 4 -> serial phase conflict-free
    __shared__ float s_mean[8], s_sd[8];
    for (int idx = tid; idx < 8 * Ck; idx += 256) {
        int rr = idx / Ck, e = idx - rr * Ck;
        int r = r0 + rr;
        rows[rr][e] = (r < M) ? in[(size_t)r * Ck + e] : 0.f;
    }
    __syncthreads();
    if (tid < 8 && r0 + tid < M) {
        const float* rw = rows[tid];
        float s = 0.f;
        for (int e = 0; e < Ck; e++) s = __fadd_rn(s, rw[e]);
        float mean = __fdiv_rn(s, 768.0f);
        float v = 0.f;
        for (int e = 0; e < Ck; e++) {
            float d = __fsub_rn(rw[e], mean);
            v = __fadd_rn(v, __fmul_rn(d, d));
        }
        s_mean[tid] = mean;
        s_sd[tid] = sqrtf(__fadd_rn(__fdiv_rn(v, 768.0f), LNEPS));
    }
    __syncthreads();
    for (int idx = tid; idx < 8 * Ck; idx += 256) {
        int rr = idx / Ck, e = idx - rr * Ck;
        int r = r0 + rr;
        if (r < M)
            out[(size_t)r * Ck + e] =
                __fadd_rn(__fmul_rn(__fdiv_rn(__fsub_rn(rows[rr][e], s_mean[rr]), s_sd[rr]), w[e]), bb[e]);
    }
}

// --------------- 128x128x16 fp32 GEMM, 8x8 per thread, k-sequential ----------
// Accumulation order per output element identical to previous gemm64
// (k ascending, single fmaf chain) => bit-identical results.
template <class Epi>
__global__ __launch_bounds__(256) void gemm128(const float* __restrict__ A,
                                               const float* __restrict__ Bm,
                                               int M, int Nn, int K, Epi epi) {
    __shared__ __align__(16) float As[16][136];
    __shared__ __align__(16) float Bs[16][128];
    int tid = threadIdx.x;
    int tx = tid & 15, ty = tid >> 4;
    int row0 = blockIdx.y * 128, col0 = blockIdx.x * 128;
    float acc[8][8] = {};
    for (int k0 = 0; k0 < K; k0 += 16) {
#pragma unroll
        for (int l = 0; l < 2; l++) {
            int idx = tid + l * 256;
            int r = idx >> 2, c4 = idx & 3;
            float4 av;
            if (row0 + r < M) av = *(const float4*)&A[(size_t)(row0 + r) * K + k0 + c4 * 4];
            else av = make_float4(0.f, 0.f, 0.f, 0.f);
            As[c4 * 4 + 0][r] = av.x;
            As[c4 * 4 + 1][r] = av.y;
            As[c4 * 4 + 2][r] = av.z;
            As[c4 * 4 + 3][r] = av.w;
        }
#pragma unroll
        for (int l = 0; l < 2; l++) {
            int idx = tid + l * 256;
            int kk = idx >> 5, c4 = idx & 31;
            *(float4*)&Bs[kk][c4 * 4] = *(const float4*)&Bm[(size_t)(k0 + kk) * Nn + col0 + c4 * 4];
        }
        __syncthreads();
#pragma unroll
        for (int kk = 0; kk < 16; kk++) {
            float a[8], bv[8];
            *(float4*)&a[0]  = *(const float4*)&As[kk][ty * 8];
            *(float4*)&a[4]  = *(const float4*)&As[kk][ty * 8 + 4];
            *(float4*)&bv[0] = *(const float4*)&Bs[kk][tx * 8];
            *(float4*)&bv[4] = *(const float4*)&Bs[kk][tx * 8 + 4];
#pragma unroll
            for (int i = 0; i < 8; i++)
#pragma unroll
                for (int j = 0; j < 8; j++)
                    acc[i][j] = fmaf(a[i], bv[j], acc[i][j]);
        }
        __syncthreads();
    }
#pragma unroll
    for (int i = 0; i < 8; i++) {
        int r = row0 + ty * 8 + i;
        if (r >= M) continue;
#pragma unroll
        for (int j = 0; j < 8; j++) epi.op(r, col0 + tx * 8 + j, acc[i][j]);
    }
}

// ------------------------- epilogues ----------------------------------------
struct EpiQKV {
    const float* policy;
    __device__ void op(int i, int j, float acc) const {
        int b = i / Nk, n = i - b * Nk;
        float val = __fmul_rn(acc, policy[i]);
        int s = j / Ck, rem = j - s * Ck;
        int h = rem >> 6, d = rem & 63;
        size_t o = (((size_t)(b * Hk + h)) * Nk + n) * DHk + d;
        if (s == 0) g_q[o] = val; else if (s == 1) g_k[o] = val; else g_v[o] = val;
    }
};
struct EpiProj {
    const float* x; const float* pb; float* out;
    __device__ void op(int i, int j, float acc) const {
        int b = i / NTk, t = i - b * NTk;
        float val = (acc + pb[j]) * g_pol[i];
        float sx;
        if (t == 0) sx = x[((size_t)b * Nk) * Ck + j];
        else {
            int u = g_ui[b * NTM1 + t - 1];
            sx = (u == NM1) ? 0.f : x[((size_t)b * Nk + g_order[b * NM1 + u] + 1) * Ck + j];
        }
        out[(size_t)i * Ck + j] = sx + val;
    }
};
struct EpiFc1 {
    const float* fb;
    __device__ void op(int i, int j, float acc) const {
        float v = acc + fb[j];
        g_hbuf[(size_t)i * FC + j] = 0.5f * v * (1.0f + erff(v * 0.70710678118654752f));
    }
};
struct EpiFc2 {
    const float* fb; float* out;
    __device__ void op(int i, int j, float acc) const {
        out[(size_t)i * Ck + j] += (acc + fb[j]) * g_pol[i];
    }
};

// --------- attention row 0, XLA-exact (seq sum, correctly-rounded exp) -------
__global__ __launch_bounds__(256) void attn_row0_kernel() {
    int bh = blockIdx.x;
    int tid = threadIdx.x;
    __shared__ float qs[64];
    __shared__ float lg[Nk];
    __shared__ float red[256];
    __shared__ float s_sum;
    const float* q0 = g_q + (size_t)bh * Nk * DHk;
    if (tid < 64) qs[tid] = q0[tid];
    __syncthreads();
    float lmax = -INFINITY;
    for (int m = tid; m < Nk; m += 256) {
        const float* kr = g_k + ((size_t)bh * Nk + m) * DHk;
        float d = 0.f;
#pragma unroll
        for (int e = 0; e < 64; e++) d = fmaf(qs[e], kr[e], d);
        d = __fmul_rn(d, SCALEF);
        lg[m] = d;
        lmax = fmaxf(lmax, d);
    }
    red[tid] = lmax; __syncthreads();
    for (int o = 128; o > 0; o >>= 1) { if (tid < o) red[tid] = fmaxf(red[tid], red[tid + o]); __syncthreads(); }
    float M = red[0]; __syncthreads();
    for (int m = tid; m < Nk; m += 256)
        lg[m] = (float)exp((double)__fsub_rn(lg[m], M));
    __syncthreads();
    if (tid == 0) {
        float s = 0.f;
        for (int m = 0; m < Nk; m++) s = __fadd_rn(s, lg[m]);
        s_sum = s;
    }
    __syncthreads();
    float S = s_sum;
    for (int m = tid; m < Nk; m += 256)
        g_attn0[bh * Nk + m] = __fdiv_rn(__fadd_rn(lg[m], EPSNF), __fadd_rn(S, SMEPS));
}

// ------- v_norm: 8 tokens/block, coalesced staging + exact serial sum --------
__global__ __launch_bounds__(256) void vnorm8_kernel() {
    int t0 = blockIdx.x * 8;
    int tid = threadIdx.x;
    __shared__ __align__(16) float buf[8][769];   // stride 769 -> conflict-free serial
    for (int idx = tid; idx < 8 * Ck; idx += 256) {
        int tt = idx / Ck, e = idx - tt * Ck;
        int i = t0 + tt;
        if (i < Bk * Nk) {
            int b = i / Nk, n = i - b * Nk;
            int h = e >> 6, d = e & 63;
            buf[tt][e] = g_v[(((size_t)(b * Hk + h)) * Nk + n) * DHk + d];
        }
    }
    __syncthreads();
    if (tid < 8 && t0 + tid < Bk * Nk) {
        const float* bw = buf[tid];
        float s = 0.f;
        for (int e = 0; e < Ck; e++) s = __fadd_rn(s, __fmul_rn(bw[e], bw[e]));
        g_vnorm[t0 + tid] = sqrtf(s);
    }
}

// ------------------------- selection chain (one block per batch) -------------
__global__ __launch_bounds__(1024) void select_kernel(float* __restrict__ out) {
    int b = blockIdx.x, tid = threadIdx.x;
    __shared__ __align__(16) float sv[1024];
    __shared__ __align__(16) int   si[1024];
    __shared__ __align__(16) float lev[1024];
    __shared__ float s_total, s_cmin, s_cmax, s_ystart;
    __shared__ int   counts[Nk];

    if (tid < NM1) {
        int n = tid + 1;
        float s = 0.f;
        for (int h = 0; h < Hk; h++) s = __fadd_rn(s, g_attn0[(b * Hk + h) * Nk + n]);
        sv[tid] = __fmul_rn(s, g_vnorm[b * Nk + n]);
        si[tid] = tid;
    } else { sv[tid] = INFINITY; si[tid] = 1 << 30; }
    __syncthreads();
    if (tid == 0) {
        float s = 0.f;
        for (int j = 0; j < NM1; j++) s = __fadd_rn(s, sv[j]);
        s_total = s;
    }
    __syncthreads();
    if (tid < NM1) sv[tid] = __fdiv_rn(sv[tid], s_total);
    __syncthreads();

    for (int k = 2; k <= 1024; k <<= 1) {
        for (int j = k >> 1; j > 0; j >>= 1) {
            int ixj = tid ^ j;
            if (ixj > tid) {
                bool up = ((tid & k) == 0);
                float v1 = sv[tid], v2 = sv[ixj];
                int   i1 = si[tid], i2 = si[ixj];
                bool lt = (v1 < v2) || (v1 == v2 && i1 < i2);
                if (lt != up) { sv[tid] = v2; sv[ixj] = v1; si[tid] = i2; si[ixj] = i1; }
            }
            __syncthreads();
        }
    }
    if (tid < NM1) g_order[b * NM1 + tid] = si[tid];
    __syncthreads();

    {
        const int nlv[10] = {784, 392, 196, 98, 49, 24, 12, 6, 3, 1};
        const int off[10] = {0,   0,   392, 592, 692, 744, 768, 780, 788, 792};
        for (int j = 1; j <= 9; j++) {
            volatile const float* par = (j == 1) ? (volatile const float*)sv
                                                 : (volatile const float*)(lev + off[j - 1]);
            float* ch = lev + off[j];
            for (int i = tid; i < nlv[j]; i += 1024) {
                float a = par[2 * i];
                float c = par[2 * i + 1];
                ch[i] = __fadd_rn(a, c);
            }
            __syncthreads();
        }
        for (int j = 8; j >= 0; j--) {
            float* par = (j == 0) ? sv : (lev + off[j]);
            volatile const float* ch = (volatile const float*)(lev + off[j + 1]);
            for (int idx = tid; idx < nlv[j]; idx += 1024) {
                int kk = (idx & 1) ? (idx >> 1) : ((idx >> 1) - 1);
                float chv = (idx == 0) ? 0.f : ch[kk];
                float pv  = par[idx];
                float val;
                if (idx == 0)      val = pv;
                else if (idx & 1)  val = chv;
                else               val = __fadd_rn(chv, pv);
                par[idx] = val;
            }
            __syncthreads();
        }
    }
    if (tid == 0) {
        float mn = 1e30f, mx = -1e30f;
        for (int j = 0; j < NM1; j++) { mn = fminf(mn, sv[j]); mx = fmaxf(mx, sv[j]); }
        s_cmin = mn; s_cmax = mx;
    }
    __syncthreads();
    if (tid < NM1) sv[tid] = __fdiv_rn(__fsub_rn(sv[tid], s_cmin), __fsub_rn(s_cmax, s_cmin));
    __syncthreads();

    lev[tid] = (tid < NM1) ? __fadd_rn(sv[tid], ((sv[tid] == 0.f) ? 1e8f : 0.f)) : 1e30f;
    __syncthreads();
    for (int o = 512; o > 0; o >>= 1) { if (tid < o) lev[tid] = fminf(lev[tid], lev[tid + o]); __syncthreads(); }
    if (tid == 0) s_ystart = lev[0];
    __syncthreads();
    float ystart = s_ystart;

    int tok = 0;
    if (tid < NM1) {
        const float delta = 1.0f / 783.0f;
        float tidf = (float)tid;
        float yl = (tid == 783) ? 1.0f : __fmul_rn(tidf, delta);
        float t1 = __fmul_rn(yl, 783.0f);
        float t2 = __fmul_rn(ystart, tidf);
        float ys = __fadd_rn(ystart, __fdiv_rn(__fsub_rn(t1, t2), 783.0f));
        float best = 1e30f; int bi = 0;
        for (int m = 0; m < NM1; m++) {
            float dd = fabsf(__fsub_rn(ys, sv[m]));
            if (dd < best) { best = dd; bi = m; }
        }
        tok = bi;
    }
    __syncthreads();

    for (int c = tid; c < Nk; c += 1024) counts[c] = 0;
    __syncthreads();
    if (tid < NM1) atomicAdd(&counts[tok], 1);
    __syncthreads();
    if (tid == 0) {
        int pos = 0;
        for (int v = 0; v < NM1; v++) {
            if (counts[v] > 0) { if (pos < NTM1) g_ui[b * NTM1 + pos] = v; pos++; }
            if (pos >= NTM1) break;
        }
        for (; pos < NTM1; pos++) g_ui[b * NTM1 + pos] = NM1;
        g_pol[b * NTk] = 1.f;
        out[OUT_POL + b * NTk] = 1.f;
        for (int k = 0; k < NTM1; k++) {
            float pv = (g_ui[b * NTM1 + k] != NM1) ? 1.f : 0.f;
            g_pol[b * NTk + 1 + k] = pv;
            out[OUT_POL + b * NTk + 1 + k] = pv;
        }
    }
}

// --------- fused attention for the 393 selected rows (continuous path) -------
__global__ __launch_bounds__(256) void attnout_kernel() {
    int tc = blockIdx.x;
    int h  = blockIdx.y;
    int b  = blockIdx.z;
    int tid = threadIdx.x;
    __shared__ float qs[8][64];
    __shared__ float pr[8][Nk];
    __shared__ int   rown[8];
    __shared__ float red[256];
    __shared__ float red2[4][512];

    if (tid < 8) {
        int t = tc * 8 + tid;
        int r = -2;
        if (t < NTk) {
            if (t == 0) r = 0;
            else {
                int u = g_ui[b * NTM1 + t - 1];
                r = (u == NM1) ? -1 : (g_order[b * NM1 + u] + 1);
            }
        }
        rown[tid] = r;
    }
    __syncthreads();
    for (int idx = tid; idx < 8 * 64; idx += 256) {
        int rr = idx >> 6, d = idx & 63;
        int r = rown[rr];
        qs[rr][d] = (r >= 0) ? g_q[(((size_t)(b * Hk + h)) * Nk + r) * DHk + d] : 0.f;
    }
    __syncthreads();

    for (int m = tid; m < Nk; m += 256) {
        const float* kr = g_k + (((size_t)(b * Hk + h)) * Nk + m) * DHk;
        float lacc[8] = {0, 0, 0, 0, 0, 0, 0, 0};
#pragma unroll
        for (int e = 0; e < 64; e++) {
            float kv = kr[e];
#pragma unroll
            for (int rr = 0; rr < 8; rr++) lacc[rr] = fmaf(qs[rr][e], kv, lacc[rr]);
        }
#pragma unroll
        for (int rr = 0; rr < 8; rr++) pr[rr][m] = lacc[rr] * SCALEF;
    }
    __syncthreads();

    for (int rr = 0; rr < 8; rr++) {
        int r = rown[rr];
        if (r < 0) {
            for (int m = tid; m < Nk; m += 256) pr[rr][m] = 0.f;
            __syncthreads();
            continue;
        }
        float lm = -1e30f;
        for (int m = tid; m < Nk; m += 256) lm = fmaxf(lm, pr[rr][m]);
        red[tid] = lm; __syncthreads();
        for (int o = 128; o > 0; o >>= 1) { if (tid < o) red[tid] = fmaxf(red[tid], red[tid + o]); __syncthreads(); }
        float M = red[0]; __syncthreads();
        float s = 0.f;
        for (int m = tid; m < Nk; m += 256) {
            float e = expf(pr[rr][m] - M);
            pr[rr][m] = e;
            s += e;
        }
        red[tid] = s; __syncthreads();
        for (int o = 128; o > 0; o >>= 1) { if (tid < o) red[tid] += red[tid + o]; __syncthreads(); }
        float S = red[0]; __syncthreads();
        for (int m = tid; m < Nk; m += 256) pr[rr][m] = (pr[rr][m] + EPSNF) / (S + SMEPS);
        __syncthreads();
    }

    int d = tid & 63, grp = tid >> 6;
    float acc[8] = {0, 0, 0, 0, 0, 0, 0, 0};
    for (int m = grp; m < Nk; m += 4) {
        float vv = g_v[(((size_t)(b * Hk + h)) * Nk + m) * DHk + d];
#pragma unroll
        for (int rr = 0; rr < 8; rr++) acc[rr] = fmaf(pr[rr][m], vv, acc[rr]);
    }
#pragma unroll
    for (int rr = 0; rr < 8; rr++) red2[grp][rr * 64 + d] = acc[rr];
    __syncthreads();
    for (int idx = tid; idx < 512; idx += 256) {
        int rr = idx >> 6, dd = idx & 63;
        int t = tc * 8 + rr;
        if (t < NTk) {
            float s = red2[0][idx] + red2[1][idx] + red2[2][idx] + red2[3][idx];
            g_attout[((size_t)(b * NTk + t)) * Ck + h * 64 + dd] = s;
        }
    }
}

// ------------------------- host orchestration --------------------------------
extern "C" void kernel_launch(void* const* d_in, const int* in_sizes, int n_in,
                              void* d_out, int out_size) {
    const float* x      = (const float*)d_in[0];
    const float* policy = (const float*)d_in[1];
    const float* n1w    = (const float*)d_in[2];
    const float* n1b    = (const float*)d_in[3];
    const float* qkvw   = (const float*)d_in[4];
    const float* projw  = (const float*)d_in[5];
    const float* projb  = (const float*)d_in[6];
    const float* n2w    = (const float*)d_in[7];
    const float* n2b    = (const float*)d_in[8];
    const float* fc1w   = (const float*)d_in[9];
    const float* fc1b   = (const float*)d_in[10];
    const float* fc2w   = (const float*)d_in[11];
    const float* fc2b   = (const float*)d_in[12];
    float* out = (float*)d_out;

    float *p_xn, *p_attout, *p_ln2, *p_h;
    cudaGetSymbolAddress((void**)&p_xn, g_xn);
    cudaGetSymbolAddress((void**)&p_attout, g_attout);
    cudaGetSymbolAddress((void**)&p_ln2, g_ln2);
    cudaGetSymbolAddress((void**)&p_h, g_hbuf);

    const int Mqkv = Bk * Nk;   // 6280
    const int Mt   = Bk * NTk;  // 3144

    ln8_kernel<<<(Mqkv + 7) / 8, 256>>>(x, p_xn, n1w, n1b, Mqkv);

    {
        EpiQKV epi{policy};
        dim3 grid((3 * Ck + 127) / 128, (Mqkv + 127) / 128);
        gemm128<EpiQKV><<<grid, 256>>>(p_xn, qkvw, Mqkv, 3 * Ck, Ck, epi);
    }

    attn_row0_kernel<<<Bk * Hk, 256>>>();
    vnorm8_kernel<<<(Bk * Nk + 7) / 8, 256>>>();

    select_kernel<<<Bk, 1024>>>(out);

    {
        dim3 grid((NTk + 7) / 8, Hk, Bk);
        attnout_kernel<<<grid, 256>>>();
    }

    {
        EpiProj epi{x, projb, out};
        dim3 grid((Ck + 127) / 128, (Mt + 127) / 128);
        gemm128<EpiProj><<<grid, 256>>>(p_attout, projw, Mt, Ck, Ck, epi);
    }

    ln8_kernel<<<(Mt + 7) / 8, 256>>>(out, p_ln2, n2w, n2b, Mt);

    {
        EpiFc1 epi{fc1b};
        dim3 grid((FC + 127) / 128, (Mt + 127) / 128);
        gemm128<EpiFc1><<<grid, 256>>>(p_ln2, fc1w, Mt, FC, Ck, epi);
    }

    {
        EpiFc2 epi{fc2b, out};
        dim3 grid((Ck + 127) / 128, (Mt + 127) / 128);
        gemm128<EpiFc2><<<grid, 256>>>(p_h, fc2w, Mt, Ck, FC, epi);
    }
    (void)in_sizes; (void)n_in; (void)out_size;
}

// round 8
// speedup vs baseline: 1.1005x; 1.0409x over previous
#include <cuda_runtime.h>
#include <math.h>
#include <stdint.h>

#define Bk   8
#define Nk   785
#define Ck   768
#define Hk   12
#define DHk  64
#define NTk  393
#define NM1  784
#define NTM1 392
#define FC   3072
#define SCALEF 0.125f
#define LNEPS 1e-5f
#define SMEPS 1e-6f
#define OUT_POL (Bk*NTk*Ck)
#define EPSNF ((float)(1e-6/785.0))

// ------------------------- scratch (static device, no allocs) ----------------
__device__ __align__(16) float g_xn[Bk*Nk*Ck];
__device__ __align__(16) float g_q[Bk*Hk*Nk*DHk];
__device__ __align__(16) float g_k[Bk*Hk*Nk*DHk];
__device__ __align__(16) float g_v[Bk*Hk*Nk*DHk];
__device__ __align__(16) float g_attn0[Bk*Hk*Nk];
__device__ __align__(16) float g_vnorm[Bk*Nk];
__device__ __align__(16) int   g_order[Bk*NM1];
__device__ __align__(16) int   g_ui[Bk*NTM1];
__device__ __align__(16) float g_pol[Bk*NTk];
__device__ __align__(16) float g_attout[(size_t)Bk*NTk*Ck];
__device__ __align__(16) float g_ln2[(size_t)Bk*NTk*Ck];
__device__ __align__(16) float g_hbuf[(size_t)Bk*NTk*FC];

// ------------- LayerNorm, XLA-exact, 8 rows/block (coalesced staging) --------
__global__ __launch_bounds__(256) void ln8_kernel(const float* __restrict__ in,
                                                  float* __restrict__ out,
                                                  const float* __restrict__ w,
                                                  const float* __restrict__ bb,
                                                  int M) {
    int r0 = blockIdx.x * 8;
    int tid = threadIdx.x;
    __shared__ __align__(16) float rows[8][772];
    __shared__ float s_mean[8], s_sd[8];
    for (int idx = tid; idx < 8 * Ck; idx += 256) {
        int rr = idx / Ck, e = idx - rr * Ck;
        int r = r0 + rr;
        rows[rr][e] = (r < M) ? in[(size_t)r * Ck + e] : 0.f;
    }
    __syncthreads();
    if (tid < 8 && r0 + tid < M) {
        const float* rw = rows[tid];
        float s = 0.f;
        for (int e = 0; e < Ck; e++) s = __fadd_rn(s, rw[e]);
        float mean = __fdiv_rn(s, 768.0f);
        float v = 0.f;
        for (int e = 0; e < Ck; e++) {
            float d = __fsub_rn(rw[e], mean);
            v = __fadd_rn(v, __fmul_rn(d, d));
        }
        s_mean[tid] = mean;
        s_sd[tid] = sqrtf(__fadd_rn(__fdiv_rn(v, 768.0f), LNEPS));
    }
    __syncthreads();
    for (int idx = tid; idx < 8 * Ck; idx += 256) {
        int rr = idx / Ck, e = idx - rr * Ck;
        int r = r0 + rr;
        if (r < M)
            out[(size_t)r * Ck + e] =
                __fadd_rn(__fmul_rn(__fdiv_rn(__fsub_rn(rows[rr][e], s_mean[rr]), s_sd[rr]), w[e]), bb[e]);
    }
}

// --------------- 128x128x16 fp32 GEMM (bit-exact path, k-sequential) ---------
template <class Epi>
__global__ __launch_bounds__(256) void gemm128(const float* __restrict__ A,
                                               const float* __restrict__ Bm,
                                               int M, int Nn, int K, Epi epi) {
    __shared__ __align__(16) float As[16][136];
    __shared__ __align__(16) float Bs[16][128];
    int tid = threadIdx.x;
    int tx = tid & 15, ty = tid >> 4;
    int row0 = blockIdx.y * 128, col0 = blockIdx.x * 128;
    float acc[8][8] = {};
    for (int k0 = 0; k0 < K; k0 += 16) {
#pragma unroll
        for (int l = 0; l < 2; l++) {
            int idx = tid + l * 256;
            int r = idx >> 2, c4 = idx & 3;
            float4 av;
            if (row0 + r < M) av = *(const float4*)&A[(size_t)(row0 + r) * K + k0 + c4 * 4];
            else av = make_float4(0.f, 0.f, 0.f, 0.f);
            As[c4 * 4 + 0][r] = av.x;
            As[c4 * 4 + 1][r] = av.y;
            As[c4 * 4 + 2][r] = av.z;
            As[c4 * 4 + 3][r] = av.w;
        }
#pragma unroll
        for (int l = 0; l < 2; l++) {
            int idx = tid + l * 256;
            int kk = idx >> 5, c4 = idx & 31;
            *(float4*)&Bs[kk][c4 * 4] = *(const float4*)&Bm[(size_t)(k0 + kk) * Nn + col0 + c4 * 4];
        }
        __syncthreads();
#pragma unroll
        for (int kk = 0; kk < 16; kk++) {
            float a[8], bv[8];
            *(float4*)&a[0]  = *(const float4*)&As[kk][ty * 8];
            *(float4*)&a[4]  = *(const float4*)&As[kk][ty * 8 + 4];
            *(float4*)&bv[0] = *(const float4*)&Bs[kk][tx * 8];
            *(float4*)&bv[4] = *(const float4*)&Bs[kk][tx * 8 + 4];
#pragma unroll
            for (int i = 0; i < 8; i++)
#pragma unroll
                for (int j = 0; j < 8; j++)
                    acc[i][j] = fmaf(a[i], bv[j], acc[i][j]);
        }
        __syncthreads();
    }
#pragma unroll
    for (int i = 0; i < 8; i++) {
        int r = row0 + ty * 8 + i;
        if (r >= M) continue;
#pragma unroll
        for (int j = 0; j < 8; j++) epi.op(r, col0 + tx * 8 + j, acc[i][j]);
    }
}

// ------------------- 3xTF32 tensor-core GEMM (continuous path) ---------------
__device__ __forceinline__ uint32_t f2tf32(float x) {
    uint32_t r;
    asm("cvt.rna.tf32.f32 %0, %1;" : "=r"(r) : "f"(x));
    return r;
}
__device__ __forceinline__ void mma_tf32(float c[4],
                                         uint32_t a0, uint32_t a1, uint32_t a2, uint32_t a3,
                                         uint32_t b0, uint32_t b1) {
    asm volatile(
        "mma.sync.aligned.m16n8k8.row.col.f32.tf32.tf32.f32 "
        "{%0,%1,%2,%3}, {%4,%5,%6,%7}, {%8,%9}, {%0,%1,%2,%3};"
        : "+f"(c[0]), "+f"(c[1]), "+f"(c[2]), "+f"(c[3])
        : "r"(a0), "r"(a1), "r"(a2), "r"(a3), "r"(b0), "r"(b1));
}

template <class Epi>
__global__ __launch_bounds__(256) void gemm_tf32(const float* __restrict__ A,
                                                 const float* __restrict__ Bm,
                                                 int M, int Nn, int K, Epi epi) {
    __shared__ __align__(16) float As[128][20];   // [m][k], stride 20: conflict-free frags
    __shared__ __align__(16) float Bs[16][136];   // [k][n], stride 136: conflict-free frags
    int tid = threadIdx.x;
    int warp = tid >> 5, lane = tid & 31;
    int g = lane >> 2, tig = lane & 3;
    int wm = (warp & 1) * 64, wn = (warp >> 1) * 32;
    int row0 = blockIdx.y * 128, col0 = blockIdx.x * 128;

    float c[4][4][4];
#pragma unroll
    for (int i = 0; i < 4; i++)
#pragma unroll
        for (int j = 0; j < 4; j++)
#pragma unroll
            for (int l = 0; l < 4; l++) c[i][j][l] = 0.f;

    for (int k0 = 0; k0 < K; k0 += 16) {
#pragma unroll
        for (int l = 0; l < 2; l++) {
            int idx = tid + l * 256;      // 0..511
            int r = idx >> 2, c4 = idx & 3;
            float4 av;
            if (row0 + r < M) av = *(const float4*)&A[(size_t)(row0 + r) * K + k0 + c4 * 4];
            else av = make_float4(0.f, 0.f, 0.f, 0.f);
            *(float4*)&As[r][c4 * 4] = av;
        }
#pragma unroll
        for (int l = 0; l < 2; l++) {
            int idx = tid + l * 256;
            int kk = idx >> 5, c4 = idx & 31;
            *(float4*)&Bs[kk][c4 * 4] = *(const float4*)&Bm[(size_t)(k0 + kk) * Nn + col0 + c4 * 4];
        }
        __syncthreads();
#pragma unroll
        for (int ks = 0; ks < 2; ks++) {
            int kb = ks * 8;
            uint32_t ahi[4][4], alo[4][4];
#pragma unroll
            for (int mt = 0; mt < 4; mt++) {
                int mr = wm + mt * 16 + g;
                float f0 = As[mr][kb + tig];
                float f1 = As[mr + 8][kb + tig];
                float f2 = As[mr][kb + tig + 4];
                float f3 = As[mr + 8][kb + tig + 4];
                ahi[mt][0] = f2tf32(f0); alo[mt][0] = f2tf32(__fsub_rn(f0, __uint_as_float(ahi[mt][0])));
                ahi[mt][1] = f2tf32(f1); alo[mt][1] = f2tf32(__fsub_rn(f1, __uint_as_float(ahi[mt][1])));
                ahi[mt][2] = f2tf32(f2); alo[mt][2] = f2tf32(__fsub_rn(f2, __uint_as_float(ahi[mt][2])));
                ahi[mt][3] = f2tf32(f3); alo[mt][3] = f2tf32(__fsub_rn(f3, __uint_as_float(ahi[mt][3])));
            }
            uint32_t bhi[4][2], blo[4][2];
#pragma unroll
            for (int nt = 0; nt < 4; nt++) {
                int nc = wn + nt * 8 + g;
                float f0 = Bs[kb + tig][nc];
                float f1 = Bs[kb + tig + 4][nc];
                bhi[nt][0] = f2tf32(f0); blo[nt][0] = f2tf32(__fsub_rn(f0, __uint_as_float(bhi[nt][0])));
                bhi[nt][1] = f2tf32(f1); blo[nt][1] = f2tf32(__fsub_rn(f1, __uint_as_float(bhi[nt][1])));
            }
#pragma unroll
            for (int mt = 0; mt < 4; mt++)
#pragma unroll
                for (int nt = 0; nt < 4; nt++) {
                    mma_tf32(c[mt][nt], alo[mt][0], alo[mt][1], alo[mt][2], alo[mt][3],
                             bhi[nt][0], bhi[nt][1]);
                    mma_tf32(c[mt][nt], ahi[mt][0], ahi[mt][1], ahi[mt][2], ahi[mt][3],
                             blo[nt][0], blo[nt][1]);
                    mma_tf32(c[mt][nt], ahi[mt][0], ahi[mt][1], ahi[mt][2], ahi[mt][3],
                             bhi[nt][0], bhi[nt][1]);
                }
        }
        __syncthreads();
    }
#pragma unroll
    for (int mt = 0; mt < 4; mt++) {
        int r_lo = row0 + wm + mt * 16 + g;
        int r_hi = r_lo + 8;
#pragma unroll
        for (int nt = 0; nt < 4; nt++) {
            int col = col0 + wn + nt * 8 + 2 * tig;
            if (r_lo < M) {
                epi.op(r_lo, col,     c[mt][nt][0]);
                epi.op(r_lo, col + 1, c[mt][nt][1]);
            }
            if (r_hi < M) {
                epi.op(r_hi, col,     c[mt][nt][2]);
                epi.op(r_hi, col + 1, c[mt][nt][3]);
            }
        }
    }
}

// ------------------------- epilogues ----------------------------------------
struct EpiQKV {
    const float* policy;
    __device__ void op(int i, int j, float acc) const {
        int b = i / Nk, n = i - b * Nk;
        float val = __fmul_rn(acc, policy[i]);
        int s = j / Ck, rem = j - s * Ck;
        int h = rem >> 6, d = rem & 63;
        size_t o = (((size_t)(b * Hk + h)) * Nk + n) * DHk + d;
        if (s == 0) g_q[o] = val; else if (s == 1) g_k[o] = val; else g_v[o] = val;
    }
};
struct EpiProj {
    const float* x; const float* pb; float* out;
    __device__ void op(int i, int j, float acc) const {
        int b = i / NTk, t = i - b * NTk;
        float val = (acc + pb[j]) * g_pol[i];
        float sx;
        if (t == 0) sx = x[((size_t)b * Nk) * Ck + j];
        else {
            int u = g_ui[b * NTM1 + t - 1];
            sx = (u == NM1) ? 0.f : x[((size_t)b * Nk + g_order[b * NM1 + u] + 1) * Ck + j];
        }
        out[(size_t)i * Ck + j] = sx + val;
    }
};
struct EpiFc1 {
    const float* fb;
    __device__ void op(int i, int j, float acc) const {
        float v = acc + fb[j];
        g_hbuf[(size_t)i * FC + j] = 0.5f * v * (1.0f + erff(v * 0.70710678118654752f));
    }
};
struct EpiFc2 {
    const float* fb; float* out;
    __device__ void op(int i, int j, float acc) const {
        out[(size_t)i * Ck + j] += (acc + fb[j]) * g_pol[i];
    }
};

// --------- attention row 0, XLA-exact (seq sum, correctly-rounded exp) -------
__global__ __launch_bounds__(256) void attn_row0_kernel() {
    int bh = blockIdx.x;
    int tid = threadIdx.x;
    __shared__ float qs[64];
    __shared__ float lg[Nk];
    __shared__ float red[256];
    __shared__ float s_sum;
    const float* q0 = g_q + (size_t)bh * Nk * DHk;
    if (tid < 64) qs[tid] = q0[tid];
    __syncthreads();
    float lmax = -INFINITY;
    for (int m = tid; m < Nk; m += 256) {
        const float* kr = g_k + ((size_t)bh * Nk + m) * DHk;
        float d = 0.f;
#pragma unroll
        for (int e = 0; e < 64; e++) d = fmaf(qs[e], kr[e], d);
        d = __fmul_rn(d, SCALEF);
        lg[m] = d;
        lmax = fmaxf(lmax, d);
    }
    red[tid] = lmax; __syncthreads();
    for (int o = 128; o > 0; o >>= 1) { if (tid < o) red[tid] = fmaxf(red[tid], red[tid + o]); __syncthreads(); }
    float M = red[0]; __syncthreads();
    for (int m = tid; m < Nk; m += 256)
        lg[m] = (float)exp((double)__fsub_rn(lg[m], M));
    __syncthreads();
    if (tid == 0) {
        float s = 0.f;
        for (int m = 0; m < Nk; m++) s = __fadd_rn(s, lg[m]);
        s_sum = s;
    }
    __syncthreads();
    float S = s_sum;
    for (int m = tid; m < Nk; m += 256)
        g_attn0[bh * Nk + m] = __fdiv_rn(__fadd_rn(lg[m], EPSNF), __fadd_rn(S, SMEPS));
}

// ------- v_norm: 8 tokens/block, coalesced staging + exact serial sum --------
__global__ __launch_bounds__(256) void vnorm8_kernel() {
    int t0 = blockIdx.x * 8;
    int tid = threadIdx.x;
    __shared__ __align__(16) float buf[8][769];
    for (int idx = tid; idx < 8 * Ck; idx += 256) {
        int tt = idx / Ck, e = idx - tt * Ck;
        int i = t0 + tt;
        if (i < Bk * Nk) {
            int b = i / Nk, n = i - b * Nk;
            int h = e >> 6, d = e & 63;
            buf[tt][e] = g_v[(((size_t)(b * Hk + h)) * Nk + n) * DHk + d];
        }
    }
    __syncthreads();
    if (tid < 8 && t0 + tid < Bk * Nk) {
        const float* bw = buf[tid];
        float s = 0.f;
        for (int e = 0; e < Ck; e++) s = __fadd_rn(s, __fmul_rn(bw[e], bw[e]));
        g_vnorm[t0 + tid] = sqrtf(s);
    }
}

// ------------------------- selection chain (one block per batch) -------------
__global__ __launch_bounds__(1024) void select_kernel(float* __restrict__ out) {
    int b = blockIdx.x, tid = threadIdx.x;
    __shared__ __align__(16) float sv[1024];
    __shared__ __align__(16) int   si[1024];
    __shared__ __align__(16) float lev[1024];
    __shared__ float s_total, s_cmin, s_cmax, s_ystart;
    __shared__ int   counts[Nk];

    if (tid < NM1) {
        int n = tid + 1;
        float s = 0.f;
        for (int h = 0; h < Hk; h++) s = __fadd_rn(s, g_attn0[(b * Hk + h) * Nk + n]);
        sv[tid] = __fmul_rn(s, g_vnorm[b * Nk + n]);
        si[tid] = tid;
    } else { sv[tid] = INFINITY; si[tid] = 1 << 30; }
    __syncthreads();
    if (tid == 0) {
        float s = 0.f;
        for (int j = 0; j < NM1; j++) s = __fadd_rn(s, sv[j]);
        s_total = s;
    }
    __syncthreads();
    if (tid < NM1) sv[tid] = __fdiv_rn(sv[tid], s_total);
    __syncthreads();

    for (int k = 2; k <= 1024; k <<= 1) {
        for (int j = k >> 1; j > 0; j >>= 1) {
            int ixj = tid ^ j;
            if (ixj > tid) {
                bool up = ((tid & k) == 0);
                float v1 = sv[tid], v2 = sv[ixj];
                int   i1 = si[tid], i2 = si[ixj];
                bool lt = (v1 < v2) || (v1 == v2 && i1 < i2);
                if (lt != up) { sv[tid] = v2; sv[ixj] = v1; si[tid] = i2; si[ixj] = i1; }
            }
            __syncthreads();
        }
    }
    if (tid < NM1) g_order[b * NM1 + tid] = si[tid];
    __syncthreads();

    {
        const int nlv[10] = {784, 392, 196, 98, 49, 24, 12, 6, 3, 1};
        const int off[10] = {0,   0,   392, 592, 692, 744, 768, 780, 788, 792};
        for (int j = 1; j <= 9; j++) {
            volatile const float* par = (j == 1) ? (volatile const float*)sv
                                                 : (volatile const float*)(lev + off[j - 1]);
            float* ch = lev + off[j];
            for (int i = tid; i < nlv[j]; i += 1024) {
                float a = par[2 * i];
                float c = par[2 * i + 1];
                ch[i] = __fadd_rn(a, c);
            }
            __syncthreads();
        }
        for (int j = 8; j >= 0; j--) {
            float* par = (j == 0) ? sv : (lev + off[j]);
            volatile const float* ch = (volatile const float*)(lev + off[j + 1]);
            for (int idx = tid; idx < nlv[j]; idx += 1024) {
                int kk = (idx & 1) ? (idx >> 1) : ((idx >> 1) - 1);
                float chv = (idx == 0) ? 0.f : ch[kk];
                float pv  = par[idx];
                float val;
                if (idx == 0)      val = pv;
                else if (idx & 1)  val = chv;
                else               val = __fadd_rn(chv, pv);
                par[idx] = val;
            }
            __syncthreads();
        }
    }
    if (tid == 0) {
        float mn = 1e30f, mx = -1e30f;
        for (int j = 0; j < NM1; j++) { mn = fminf(mn, sv[j]); mx = fmaxf(mx, sv[j]); }
        s_cmin = mn; s_cmax = mx;
    }
    __syncthreads();
    if (tid < NM1) sv[tid] = __fdiv_rn(__fsub_rn(sv[tid], s_cmin), __fsub_rn(s_cmax, s_cmin));
    __syncthreads();

    lev[tid] = (tid < NM1) ? __fadd_rn(sv[tid], ((sv[tid] == 0.f) ? 1e8f : 0.f)) : 1e30f;
    __syncthreads();
    for (int o = 512; o > 0; o >>= 1) { if (tid < o) lev[tid] = fminf(lev[tid], lev[tid + o]); __syncthreads(); }
    if (tid == 0) s_ystart = lev[0];
    __syncthreads();
    float ystart = s_ystart;

    int tok = 0;
    if (tid < NM1) {
        const float delta = 1.0f / 783.0f;
        float tidf = (float)tid;
        float yl = (tid == 783) ? 1.0f : __fmul_rn(tidf, delta);
        float t1 = __fmul_rn(yl, 783.0f);
        float t2 = __fmul_rn(ystart, tidf);
        float ys = __fadd_rn(ystart, __fdiv_rn(__fsub_rn(t1, t2), 783.0f));
        float best = 1e30f; int bi = 0;
        for (int m = 0; m < NM1; m++) {
            float dd = fabsf(__fsub_rn(ys, sv[m]));
            if (dd < best) { best = dd; bi = m; }
        }
        tok = bi;
    }
    __syncthreads();

    for (int c = tid; c < Nk; c += 1024) counts[c] = 0;
    __syncthreads();
    if (tid < NM1) atomicAdd(&counts[tok], 1);
    __syncthreads();
    if (tid == 0) {
        int pos = 0;
        for (int v = 0; v < NM1; v++) {
            if (counts[v] > 0) { if (pos < NTM1) g_ui[b * NTM1 + pos] = v; pos++; }
            if (pos >= NTM1) break;
        }
        for (; pos < NTM1; pos++) g_ui[b * NTM1 + pos] = NM1;
        g_pol[b * NTk] = 1.f;
        out[OUT_POL + b * NTk] = 1.f;
        for (int k = 0; k < NTM1; k++) {
            float pv = (g_ui[b * NTM1 + k] != NM1) ? 1.f : 0.f;
            g_pol[b * NTk + 1 + k] = pv;
            out[OUT_POL + b * NTk + 1 + k] = pv;
        }
    }
}

// --------- fused attention for the 393 selected rows (continuous path) -------
__global__ __launch_bounds__(256) void attnout_kernel() {
    int tc = blockIdx.x;
    int h  = blockIdx.y;
    int b  = blockIdx.z;
    int tid = threadIdx.x;
    __shared__ float qs[8][64];
    __shared__ float pr[8][Nk];
    __shared__ int   rown[8];
    __shared__ float red[256];
    __shared__ float red2[4][512];

    if (tid < 8) {
        int t = tc * 8 + tid;
        int r = -2;
        if (t < NTk) {
            if (t == 0) r = 0;
            else {
                int u = g_ui[b * NTM1 + t - 1];
                r = (u == NM1) ? -1 : (g_order[b * NM1 + u] + 1);
            }
        }
        rown[tid] = r;
    }
    __syncthreads();
    for (int idx = tid; idx < 8 * 64; idx += 256) {
        int rr = idx >> 6, d = idx & 63;
        int r = rown[rr];
        qs[rr][d] = (r >= 0) ? g_q[(((size_t)(b * Hk + h)) * Nk + r) * DHk + d] : 0.f;
    }
    __syncthreads();

    for (int m = tid; m < Nk; m += 256) {
        const float* kr = g_k + (((size_t)(b * Hk + h)) * Nk + m) * DHk;
        float lacc[8] = {0, 0, 0, 0, 0, 0, 0, 0};
#pragma unroll
        for (int e = 0; e < 64; e++) {
            float kv = kr[e];
#pragma unroll
            for (int rr = 0; rr < 8; rr++) lacc[rr] = fmaf(qs[rr][e], kv, lacc[rr]);
        }
#pragma unroll
        for (int rr = 0; rr < 8; rr++) pr[rr][m] = lacc[rr] * SCALEF;
    }
    __syncthreads();

    for (int rr = 0; rr < 8; rr++) {
        int r = rown[rr];
        if (r < 0) {
            for (int m = tid; m < Nk; m += 256) pr[rr][m] = 0.f;
            __syncthreads();
            continue;
        }
        float lm = -1e30f;
        for (int m = tid; m < Nk; m += 256) lm = fmaxf(lm, pr[rr][m]);
        red[tid] = lm; __syncthreads();
        for (int o = 128; o > 0; o >>= 1) { if (tid < o) red[tid] = fmaxf(red[tid], red[tid + o]); __syncthreads(); }
        float M = red[0]; __syncthreads();
        float s = 0.f;
        for (int m = tid; m < Nk; m += 256) {
            float e = expf(pr[rr][m] - M);
            pr[rr][m] = e;
            s += e;
        }
        red[tid] = s; __syncthreads();
        for (int o = 128; o > 0; o >>= 1) { if (tid < o) red[tid] += red[tid + o]; __syncthreads(); }
        float S = red[0]; __syncthreads();
        for (int m = tid; m < Nk; m += 256) pr[rr][m] = (pr[rr][m] + EPSNF) / (S + SMEPS);
        __syncthreads();
    }

    int d = tid & 63, grp = tid >> 6;
    float acc[8] = {0, 0, 0, 0, 0, 0, 0, 0};
    for (int m = grp; m < Nk; m += 4) {
        float vv = g_v[(((size_t)(b * Hk + h)) * Nk + m) * DHk + d];
#pragma unroll
        for (int rr = 0; rr < 8; rr++) acc[rr] = fmaf(pr[rr][m], vv, acc[rr]);
    }
#pragma unroll
    for (int rr = 0; rr < 8; rr++) red2[grp][rr * 64 + d] = acc[rr];
    __syncthreads();
    for (int idx = tid; idx < 512; idx += 256) {
        int rr = idx >> 6, dd = idx & 63;
        int t = tc * 8 + rr;
        if (t < NTk) {
            float s = red2[0][idx] + red2[1][idx] + red2[2][idx] + red2[3][idx];
            g_attout[((size_t)(b * NTk + t)) * Ck + h * 64 + dd] = s;
        }
    }
}

// ------------------------- host orchestration --------------------------------
extern "C" void kernel_launch(void* const* d_in, const int* in_sizes, int n_in,
                              void* d_out, int out_size) {
    const float* x      = (const float*)d_in[0];
    const float* policy = (const float*)d_in[1];
    const float* n1w    = (const float*)d_in[2];
    const float* n1b    = (const float*)d_in[3];
    const float* qkvw   = (const float*)d_in[4];
    const float* projw  = (const float*)d_in[5];
    const float* projb  = (const float*)d_in[6];
    const float* n2w    = (const float*)d_in[7];
    const float* n2b    = (const float*)d_in[8];
    const float* fc1w   = (const float*)d_in[9];
    const float* fc1b   = (const float*)d_in[10];
    const float* fc2w   = (const float*)d_in[11];
    const float* fc2b   = (const float*)d_in[12];
    float* out = (float*)d_out;

    float *p_xn, *p_attout, *p_ln2, *p_h;
    cudaGetSymbolAddress((void**)&p_xn, g_xn);
    cudaGetSymbolAddress((void**)&p_attout, g_attout);
    cudaGetSymbolAddress((void**)&p_ln2, g_ln2);
    cudaGetSymbolAddress((void**)&p_h, g_hbuf);

    const int Mqkv = Bk * Nk;   // 6280
    const int Mt   = Bk * NTk;  // 3144

    ln8_kernel<<<(Mqkv + 7) / 8, 256>>>(x, p_xn, n1w, n1b, Mqkv);

    {   // bit-exact FFMA path (feeds decisions)
        EpiQKV epi{policy};
        dim3 grid((3 * Ck + 127) / 128, (Mqkv + 127) / 128);
        gemm128<EpiQKV><<<grid, 256>>>(p_xn, qkvw, Mqkv, 3 * Ck, Ck, epi);
    }

    attn_row0_kernel<<<Bk * Hk, 256>>>();
    vnorm8_kernel<<<(Bk * Nk + 7) / 8, 256>>>();

    select_kernel<<<Bk, 1024>>>(out);

    {
        dim3 grid((NTk + 7) / 8, Hk, Bk);
        attnout_kernel<<<grid, 256>>>();
    }

    {   // continuous path: 3xTF32 tensor cores
        EpiProj epi{x, projb, out};
        dim3 grid(Ck / 128, (Mt + 127) / 128);
        gemm_tf32<EpiProj><<<grid, 256>>>(p_attout, projw, Mt, Ck, Ck, epi);
    }

    ln8_kernel<<<(Mt + 7) / 8, 256>>>(out, p_ln2, n2w, n2b, Mt);

    {
        EpiFc1 epi{fc1b};
        dim3 grid(FC / 128, (Mt + 127) / 128);
        gemm_tf32<EpiFc1><<<grid, 256>>>(p_ln2, fc1w, Mt, FC, Ck, epi);
    }

    {
        EpiFc2 epi{fc2b, out};
        dim3 grid(Ck / 128, (Mt + 127) / 128);
        gemm_tf32<EpiFc2><<<grid, 256>>>(p_h, fc2w, Mt, Ck, FC, epi);
    }
    (void)in_sizes; (void)n_in; (void)out_size;
}

// round 9
// speedup vs baseline: 1.1274x; 1.0244x over previous
#include <cuda_runtime.h>
#include <cuda_bf16.h>
#include <math.h>
#include <stdint.h>

#define Bk   8
#define Nk   785
#define Ck   768
#define Hk   12
#define DHk  64
#define NTk  393
#define NM1  784
#define NTM1 392
#define FC   3072
#define SCALEF 0.125f
#define LNEPS 1e-5f
#define SMEPS 1e-6f
#define OUT_POL (Bk*NTk*Ck)
#define EPSNF ((float)(1e-6/785.0))

// ------------------------- scratch (static device, no allocs) ----------------
__device__ __align__(16) float g_xn[Bk*Nk*Ck];
__device__ __align__(16) float g_q[Bk*Hk*Nk*DHk];
__device__ __align__(16) float g_k[Bk*Hk*Nk*DHk];
__device__ __align__(16) float g_v[Bk*Hk*Nk*DHk];
__device__ __align__(16) float g_attn0[Bk*Hk*Nk];
__device__ __align__(16) float g_vnorm[Bk*Nk];
__device__ __align__(16) int   g_order[Bk*NM1];
__device__ __align__(16) int   g_ui[Bk*NTM1];
__device__ __align__(16) float g_pol[Bk*NTk];
__device__ __align__(16) float g_attout[(size_t)Bk*NTk*Ck];
__device__ __align__(16) float g_ln2[(size_t)Bk*NTk*Ck];
__device__ __align__(16) float g_hbuf[(size_t)Bk*NTk*FC];

// ------------- LayerNorm, XLA-exact, 8 rows/block (coalesced staging) --------
__global__ __launch_bounds__(256) void ln8_kernel(const float* __restrict__ in,
                                                  float* __restrict__ out,
                                                  const float* __restrict__ w,
                                                  const float* __restrict__ bb,
                                                  int M) {
    int r0 = blockIdx.x * 8;
    int tid = threadIdx.x;
    __shared__ __align__(16) float rows[8][772];
    __shared__ float s_mean[8], s_sd[8];
    for (int idx = tid; idx < 8 * Ck; idx += 256) {
        int rr = idx / Ck, e = idx - rr * Ck;
        int r = r0 + rr;
        rows[rr][e] = (r < M) ? in[(size_t)r * Ck + e] : 0.f;
    }
    __syncthreads();
    if (tid < 8 && r0 + tid < M) {
        const float* rw = rows[tid];
        float s = 0.f;
        for (int e = 0; e < Ck; e++) s = __fadd_rn(s, rw[e]);
        float mean = __fdiv_rn(s, 768.0f);
        float v = 0.f;
        for (int e = 0; e < Ck; e++) {
            float d = __fsub_rn(rw[e], mean);
            v = __fadd_rn(v, __fmul_rn(d, d));
        }
        s_mean[tid] = mean;
        s_sd[tid] = sqrtf(__fadd_rn(__fdiv_rn(v, 768.0f), LNEPS));
    }
    __syncthreads();
    for (int idx = tid; idx < 8 * Ck; idx += 256) {
        int rr = idx / Ck, e = idx - rr * Ck;
        int r = r0 + rr;
        if (r < M)
            out[(size_t)r * Ck + e] =
                __fadd_rn(__fmul_rn(__fdiv_rn(__fsub_rn(rows[rr][e], s_mean[rr]), s_sd[rr]), w[e]), bb[e]);
    }
}

// --------------- 128x128x16 fp32 GEMM (bit-exact path, k-sequential) ---------
template <class Epi>
__global__ __launch_bounds__(256) void gemm128(const float* __restrict__ A,
                                               const float* __restrict__ Bm,
                                               int M, int Nn, int K, Epi epi) {
    __shared__ __align__(16) float As[16][136];
    __shared__ __align__(16) float Bs[16][128];
    int tid = threadIdx.x;
    int tx = tid & 15, ty = tid >> 4;
    int row0 = blockIdx.y * 128, col0 = blockIdx.x * 128;
    float acc[8][8] = {};
    for (int k0 = 0; k0 < K; k0 += 16) {
#pragma unroll
        for (int l = 0; l < 2; l++) {
            int idx = tid + l * 256;
            int r = idx >> 2, c4 = idx & 3;
            float4 av;
            if (row0 + r < M) av = *(const float4*)&A[(size_t)(row0 + r) * K + k0 + c4 * 4];
            else av = make_float4(0.f, 0.f, 0.f, 0.f);
            As[c4 * 4 + 0][r] = av.x;
            As[c4 * 4 + 1][r] = av.y;
            As[c4 * 4 + 2][r] = av.z;
            As[c4 * 4 + 3][r] = av.w;
        }
#pragma unroll
        for (int l = 0; l < 2; l++) {
            int idx = tid + l * 256;
            int kk = idx >> 5, c4 = idx & 31;
            *(float4*)&Bs[kk][c4 * 4] = *(const float4*)&Bm[(size_t)(k0 + kk) * Nn + col0 + c4 * 4];
        }
        __syncthreads();
#pragma unroll
        for (int kk = 0; kk < 16; kk++) {
            float a[8], bv[8];
            *(float4*)&a[0]  = *(const float4*)&As[kk][ty * 8];
            *(float4*)&a[4]  = *(const float4*)&As[kk][ty * 8 + 4];
            *(float4*)&bv[0] = *(const float4*)&Bs[kk][tx * 8];
            *(float4*)&bv[4] = *(const float4*)&Bs[kk][tx * 8 + 4];
#pragma unroll
            for (int i = 0; i < 8; i++)
#pragma unroll
                for (int j = 0; j < 8; j++)
                    acc[i][j] = fmaf(a[i], bv[j], acc[i][j]);
        }
        __syncthreads();
    }
#pragma unroll
    for (int i = 0; i < 8; i++) {
        int r = row0 + ty * 8 + i;
        if (r >= M) continue;
#pragma unroll
        for (int j = 0; j < 8; j++) epi.op(r, col0 + tx * 8 + j, acc[i][j]);
    }
}

// ------------- 3-split BF16 tensor-core GEMM (continuous path) ---------------
// x = hi + lo + O(2^-16 x); D = Ahi*Bhi + Ahi*Blo + Alo*Bhi  (drop lo*lo)
__device__ __forceinline__ void bsplit2(float x0, float x1, uint32_t& hi, uint32_t& lo) {
    __nv_bfloat16 h0 = __float2bfloat16_rn(x0);
    __nv_bfloat16 h1 = __float2bfloat16_rn(x1);
    __nv_bfloat16 l0 = __float2bfloat16_rn(__fsub_rn(x0, __bfloat162float(h0)));
    __nv_bfloat16 l1 = __float2bfloat16_rn(__fsub_rn(x1, __bfloat162float(h1)));
    __nv_bfloat162 hp(h0, h1), lp(l0, l1);
    hi = *reinterpret_cast<uint32_t*>(&hp);
    lo = *reinterpret_cast<uint32_t*>(&lp);
}
__device__ __forceinline__ void mma_bf16(float c[4],
                                         uint32_t a0, uint32_t a1, uint32_t a2, uint32_t a3,
                                         uint32_t b0, uint32_t b1) {
    asm volatile(
        "mma.sync.aligned.m16n8k16.row.col.f32.bf16.bf16.f32 "
        "{%0,%1,%2,%3}, {%4,%5,%6,%7}, {%8,%9}, {%0,%1,%2,%3};"
        : "+f"(c[0]), "+f"(c[1]), "+f"(c[2]), "+f"(c[3])
        : "r"(a0), "r"(a1), "r"(a2), "r"(a3), "r"(b0), "r"(b1));
}

template <class Epi>
__global__ __launch_bounds__(256) void gemm_bf16s(const float* __restrict__ A,
                                                  const float* __restrict__ Bm,
                                                  int M, int Nn, int K, Epi epi) {
    __shared__ __align__(16) float As[128][20];   // [m][k]
    __shared__ __align__(16) float Bs[16][132];   // [k][n], stride 132: conflict-free
    int tid = threadIdx.x;
    int warp = tid >> 5, lane = tid & 31;
    int g = lane >> 2, tig = lane & 3;
    int wm = (warp & 1) * 64, wn = (warp >> 1) * 32;
    int row0 = blockIdx.y * 128, col0 = blockIdx.x * 128;

    float c[4][4][4];
#pragma unroll
    for (int i = 0; i < 4; i++)
#pragma unroll
        for (int j = 0; j < 4; j++)
#pragma unroll
            for (int l = 0; l < 4; l++) c[i][j][l] = 0.f;

    for (int k0 = 0; k0 < K; k0 += 16) {
#pragma unroll
        for (int l = 0; l < 2; l++) {
            int idx = tid + l * 256;      // 0..511
            int r = idx >> 2, c4 = idx & 3;
            float4 av;
            if (row0 + r < M) av = *(const float4*)&A[(size_t)(row0 + r) * K + k0 + c4 * 4];
            else av = make_float4(0.f, 0.f, 0.f, 0.f);
            *(float4*)&As[r][c4 * 4] = av;
        }
#pragma unroll
        for (int l = 0; l < 2; l++) {
            int idx = tid + l * 256;
            int kk = idx >> 5, c4 = idx & 31;
            *(float4*)&Bs[kk][c4 * 4] = *(const float4*)&Bm[(size_t)(k0 + kk) * Nn + col0 + c4 * 4];
        }
        __syncthreads();

        uint32_t ahi[4][4], alo[4][4];
#pragma unroll
        for (int mt = 0; mt < 4; mt++) {
            int mr = wm + mt * 16 + g;
            float2 p0 = *(const float2*)&As[mr][2 * tig];           // a0: k=2t,2t+1
            float2 p1 = *(const float2*)&As[mr + 8][2 * tig];       // a1
            float2 p2 = *(const float2*)&As[mr][2 * tig + 8];       // a2
            float2 p3 = *(const float2*)&As[mr + 8][2 * tig + 8];   // a3
            bsplit2(p0.x, p0.y, ahi[mt][0], alo[mt][0]);
            bsplit2(p1.x, p1.y, ahi[mt][1], alo[mt][1]);
            bsplit2(p2.x, p2.y, ahi[mt][2], alo[mt][2]);
            bsplit2(p3.x, p3.y, ahi[mt][3], alo[mt][3]);
        }
        uint32_t bhi[4][2], blo[4][2];
#pragma unroll
        for (int nt = 0; nt < 4; nt++) {
            int nc = wn + nt * 8 + g;
            float q0 = Bs[2 * tig][nc];
            float q1 = Bs[2 * tig + 1][nc];
            float q2 = Bs[2 * tig + 8][nc];
            float q3 = Bs[2 * tig + 9][nc];
            bsplit2(q0, q1, bhi[nt][0], blo[nt][0]);
            bsplit2(q2, q3, bhi[nt][1], blo[nt][1]);
        }
#pragma unroll
        for (int mt = 0; mt < 4; mt++)
#pragma unroll
            for (int nt = 0; nt < 4; nt++) {
                mma_bf16(c[mt][nt], alo[mt][0], alo[mt][1], alo[mt][2], alo[mt][3],
                         bhi[nt][0], bhi[nt][1]);
                mma_bf16(c[mt][nt], ahi[mt][0], ahi[mt][1], ahi[mt][2], ahi[mt][3],
                         blo[nt][0], blo[nt][1]);
                mma_bf16(c[mt][nt], ahi[mt][0], ahi[mt][1], ahi[mt][2], ahi[mt][3],
                         bhi[nt][0], bhi[nt][1]);
            }
        __syncthreads();
    }
#pragma unroll
    for (int mt = 0; mt < 4; mt++) {
        int r_lo = row0 + wm + mt * 16 + g;
        int r_hi = r_lo + 8;
#pragma unroll
        for (int nt = 0; nt < 4; nt++) {
            int col = col0 + wn + nt * 8 + 2 * tig;
            if (r_lo < M) {
                epi.op(r_lo, col,     c[mt][nt][0]);
                epi.op(r_lo, col + 1, c[mt][nt][1]);
            }
            if (r_hi < M) {
                epi.op(r_hi, col,     c[mt][nt][2]);
                epi.op(r_hi, col + 1, c[mt][nt][3]);
            }
        }
    }
}

// ------------------------- epilogues ----------------------------------------
struct EpiQKV {
    const float* policy;
    __device__ void op(int i, int j, float acc) const {
        int b = i / Nk, n = i - b * Nk;
        float val = __fmul_rn(acc, policy[i]);
        int s = j / Ck, rem = j - s * Ck;
        int h = rem >> 6, d = rem & 63;
        size_t o = (((size_t)(b * Hk + h)) * Nk + n) * DHk + d;
        if (s == 0) g_q[o] = val; else if (s == 1) g_k[o] = val; else g_v[o] = val;
    }
};
struct EpiProj {
    const float* x; const float* pb; float* out;
    __device__ void op(int i, int j, float acc) const {
        int b = i / NTk, t = i - b * NTk;
        float val = (acc + pb[j]) * g_pol[i];
        float sx;
        if (t == 0) sx = x[((size_t)b * Nk) * Ck + j];
        else {
            int u = g_ui[b * NTM1 + t - 1];
            sx = (u == NM1) ? 0.f : x[((size_t)b * Nk + g_order[b * NM1 + u] + 1) * Ck + j];
        }
        out[(size_t)i * Ck + j] = sx + val;
    }
};
struct EpiFc1 {
    const float* fb;
    __device__ void op(int i, int j, float acc) const {
        float v = acc + fb[j];
        g_hbuf[(size_t)i * FC + j] = 0.5f * v * (1.0f + erff(v * 0.70710678118654752f));
    }
};
struct EpiFc2 {
    const float* fb; float* out;
    __device__ void op(int i, int j, float acc) const {
        out[(size_t)i * Ck + j] += (acc + fb[j]) * g_pol[i];
    }
};

// --------- attention row 0, XLA-exact (seq sum, correctly-rounded exp) -------
__global__ __launch_bounds__(256) void attn_row0_kernel() {
    int bh = blockIdx.x;
    int tid = threadIdx.x;
    __shared__ float qs[64];
    __shared__ float lg[Nk];
    __shared__ float red[256];
    __shared__ float s_sum;
    const float* q0 = g_q + (size_t)bh * Nk * DHk;
    if (tid < 64) qs[tid] = q0[tid];
    __syncthreads();
    float lmax = -INFINITY;
    for (int m = tid; m < Nk; m += 256) {
        const float* kr = g_k + ((size_t)bh * Nk + m) * DHk;
        float d = 0.f;
#pragma unroll
        for (int e = 0; e < 64; e++) d = fmaf(qs[e], kr[e], d);
        d = __fmul_rn(d, SCALEF);
        lg[m] = d;
        lmax = fmaxf(lmax, d);
    }
    red[tid] = lmax; __syncthreads();
    for (int o = 128; o > 0; o >>= 1) { if (tid < o) red[tid] = fmaxf(red[tid], red[tid + o]); __syncthreads(); }
    float M = red[0]; __syncthreads();
    for (int m = tid; m < Nk; m += 256)
        lg[m] = (float)exp((double)__fsub_rn(lg[m], M));
    __syncthreads();
    if (tid == 0) {
        float s = 0.f;
        for (int m = 0; m < Nk; m++) s = __fadd_rn(s, lg[m]);
        s_sum = s;
    }
    __syncthreads();
    float S = s_sum;
    for (int m = tid; m < Nk; m += 256)
        g_attn0[bh * Nk + m] = __fdiv_rn(__fadd_rn(lg[m], EPSNF), __fadd_rn(S, SMEPS));
}

// ------- v_norm: 8 tokens/block, coalesced staging + exact serial sum --------
__global__ __launch_bounds__(256) void vnorm8_kernel() {
    int t0 = blockIdx.x * 8;
    int tid = threadIdx.x;
    __shared__ __align__(16) float buf[8][769];
    for (int idx = tid; idx < 8 * Ck; idx += 256) {
        int tt = idx / Ck, e = idx - tt * Ck;
        int i = t0 + tt;
        if (i < Bk * Nk) {
            int b = i / Nk, n = i - b * Nk;
            int h = e >> 6, d = e & 63;
            buf[tt][e] = g_v[(((size_t)(b * Hk + h)) * Nk + n) * DHk + d];
        }
    }
    __syncthreads();
    if (tid < 8 && t0 + tid < Bk * Nk) {
        const float* bw = buf[tid];
        float s = 0.f;
        for (int e = 0; e < Ck; e++) s = __fadd_rn(s, __fmul_rn(bw[e], bw[e]));
        g_vnorm[t0 + tid] = sqrtf(s);
    }
}

// ------------------------- selection chain (one block per batch) -------------
__global__ __launch_bounds__(1024) void select_kernel(float* __restrict__ out) {
    int b = blockIdx.x, tid = threadIdx.x;
    __shared__ __align__(16) float sv[1024];
    __shared__ __align__(16) int   si[1024];
    __shared__ __align__(16) float lev[1024];
    __shared__ float s_total, s_cmin, s_cmax, s_ystart;
    __shared__ int   counts[Nk];

    if (tid < NM1) {
        int n = tid + 1;
        float s = 0.f;
        for (int h = 0; h < Hk; h++) s = __fadd_rn(s, g_attn0[(b * Hk + h) * Nk + n]);
        sv[tid] = __fmul_rn(s, g_vnorm[b * Nk + n]);
        si[tid] = tid;
    } else { sv[tid] = INFINITY; si[tid] = 1 << 30; }
    __syncthreads();
    if (tid == 0) {
        float s = 0.f;
        for (int j = 0; j < NM1; j++) s = __fadd_rn(s, sv[j]);
        s_total = s;
    }
    __syncthreads();
    if (tid < NM1) sv[tid] = __fdiv_rn(sv[tid], s_total);
    __syncthreads();

    for (int k = 2; k <= 1024; k <<= 1) {
        for (int j = k >> 1; j > 0; j >>= 1) {
            int ixj = tid ^ j;
            if (ixj > tid) {
                bool up = ((tid & k) == 0);
                float v1 = sv[tid], v2 = sv[ixj];
                int   i1 = si[tid], i2 = si[ixj];
                bool lt = (v1 < v2) || (v1 == v2 && i1 < i2);
                if (lt != up) { sv[tid] = v2; sv[ixj] = v1; si[tid] = i2; si[ixj] = i1; }
            }
            __syncthreads();
        }
    }
    if (tid < NM1) g_order[b * NM1 + tid] = si[tid];
    __syncthreads();

    {
        const int nlv[10] = {784, 392, 196, 98, 49, 24, 12, 6, 3, 1};
        const int off[10] = {0,   0,   392, 592, 692, 744, 768, 780, 788, 792};
        for (int j = 1; j <= 9; j++) {
            volatile const float* par = (j == 1) ? (volatile const float*)sv
                                                 : (volatile const float*)(lev + off[j - 1]);
            float* ch = lev + off[j];
            for (int i = tid; i < nlv[j]; i += 1024) {
                float a = par[2 * i];
                float c = par[2 * i + 1];
                ch[i] = __fadd_rn(a, c);
            }
            __syncthreads();
        }
        for (int j = 8; j >= 0; j--) {
            float* par = (j == 0) ? sv : (lev + off[j]);
            volatile const float* ch = (volatile const float*)(lev + off[j + 1]);
            for (int idx = tid; idx < nlv[j]; idx += 1024) {
                int kk = (idx & 1) ? (idx >> 1) : ((idx >> 1) - 1);
                float chv = (idx == 0) ? 0.f : ch[kk];
                float pv  = par[idx];
                float val;
                if (idx == 0)      val = pv;
                else if (idx & 1)  val = chv;
                else               val = __fadd_rn(chv, pv);
                par[idx] = val;
            }
            __syncthreads();
        }
    }
    if (tid == 0) {
        float mn = 1e30f, mx = -1e30f;
        for (int j = 0; j < NM1; j++) { mn = fminf(mn, sv[j]); mx = fmaxf(mx, sv[j]); }
        s_cmin = mn; s_cmax = mx;
    }
    __syncthreads();
    if (tid < NM1) sv[tid] = __fdiv_rn(__fsub_rn(sv[tid], s_cmin), __fsub_rn(s_cmax, s_cmin));
    __syncthreads();

    lev[tid] = (tid < NM1) ? __fadd_rn(sv[tid], ((sv[tid] == 0.f) ? 1e8f : 0.f)) : 1e30f;
    __syncthreads();
    for (int o = 512; o > 0; o >>= 1) { if (tid < o) lev[tid] = fminf(lev[tid], lev[tid + o]); __syncthreads(); }
    if (tid == 0) s_ystart = lev[0];
    __syncthreads();
    float ystart = s_ystart;

    int tok = 0;
    if (tid < NM1) {
        const float delta = 1.0f / 783.0f;
        float tidf = (float)tid;
        float yl = (tid == 783) ? 1.0f : __fmul_rn(tidf, delta);
        float t1 = __fmul_rn(yl, 783.0f);
        float t2 = __fmul_rn(ystart, tidf);
        float ys = __fadd_rn(ystart, __fdiv_rn(__fsub_rn(t1, t2), 783.0f));
        float best = 1e30f; int bi = 0;
        for (int m = 0; m < NM1; m++) {
            float dd = fabsf(__fsub_rn(ys, sv[m]));
            if (dd < best) { best = dd; bi = m; }
        }
        tok = bi;
    }
    __syncthreads();

    for (int c = tid; c < Nk; c += 1024) counts[c] = 0;
    __syncthreads();
    if (tid < NM1) atomicAdd(&counts[tok], 1);
    __syncthreads();
    if (tid == 0) {
        int pos = 0;
        for (int v = 0; v < NM1; v++) {
            if (counts[v] > 0) { if (pos < NTM1) g_ui[b * NTM1 + pos] = v; pos++; }
            if (pos >= NTM1) break;
        }
        for (; pos < NTM1; pos++) g_ui[b * NTM1 + pos] = NM1;
        g_pol[b * NTk] = 1.f;
        out[OUT_POL + b * NTk] = 1.f;
        for (int k = 0; k < NTM1; k++) {
            float pv = (g_ui[b * NTM1 + k] != NM1) ? 1.f : 0.f;
            g_pol[b * NTk + 1 + k] = pv;
            out[OUT_POL + b * NTk + 1 + k] = pv;
        }
    }
}

// --------- fused attention for the 393 selected rows (continuous path) -------
__global__ __launch_bounds__(256) void attnout_kernel() {
    int tc = blockIdx.x;
    int h  = blockIdx.y;
    int b  = blockIdx.z;
    int tid = threadIdx.x;
    __shared__ float qs[8][64];
    __shared__ float pr[8][Nk];
    __shared__ int   rown[8];
    __shared__ float red[256];
    __shared__ float red2[4][512];

    if (tid < 8) {
        int t = tc * 8 + tid;
        int r = -2;
        if (t < NTk) {
            if (t == 0) r = 0;
            else {
                int u = g_ui[b * NTM1 + t - 1];
                r = (u == NM1) ? -1 : (g_order[b * NM1 + u] + 1);
            }
        }
        rown[tid] = r;
    }
    __syncthreads();
    for (int idx = tid; idx < 8 * 64; idx += 256) {
        int rr = idx >> 6, d = idx & 63;
        int r = rown[rr];
        qs[rr][d] = (r >= 0) ? g_q[(((size_t)(b * Hk + h)) * Nk + r) * DHk + d] : 0.f;
    }
    __syncthreads();

    for (int m = tid; m < Nk; m += 256) {
        const float* kr = g_k + (((size_t)(b * Hk + h)) * Nk + m) * DHk;
        float lacc[8] = {0, 0, 0, 0, 0, 0, 0, 0};
#pragma unroll
        for (int e = 0; e < 64; e++) {
            float kv = kr[e];
#pragma unroll
            for (int rr = 0; rr < 8; rr++) lacc[rr] = fmaf(qs[rr][e], kv, lacc[rr]);
        }
#pragma unroll
        for (int rr = 0; rr < 8; rr++) pr[rr][m] = lacc[rr] * SCALEF;
    }
    __syncthreads();

    for (int rr = 0; rr < 8; rr++) {
        int r = rown[rr];
        if (r < 0) {
            for (int m = tid; m < Nk; m += 256) pr[rr][m] = 0.f;
            __syncthreads();
            continue;
        }
        float lm = -1e30f;
        for (int m = tid; m < Nk; m += 256) lm = fmaxf(lm, pr[rr][m]);
        red[tid] = lm; __syncthreads();
        for (int o = 128; o > 0; o >>= 1) { if (tid < o) red[tid] = fmaxf(red[tid], red[tid + o]); __syncthreads(); }
        float M = red[0]; __syncthreads();
        float s = 0.f;
        for (int m = tid; m < Nk; m += 256) {
            float e = expf(pr[rr][m] - M);
            pr[rr][m] = e;
            s += e;
        }
        red[tid] = s; __syncthreads();
        for (int o = 128; o > 0; o >>= 1) { if (tid < o) red[tid] += red[tid + o]; __syncthreads(); }
        float S = red[0]; __syncthreads();
        for (int m = tid; m < Nk; m += 256) pr[rr][m] = (pr[rr][m] + EPSNF) / (S + SMEPS);
        __syncthreads();
    }

    int d = tid & 63, grp = tid >> 6;
    float acc[8] = {0, 0, 0, 0, 0, 0, 0, 0};
    for (int m = grp; m < Nk; m += 4) {
        float vv = g_v[(((size_t)(b * Hk + h)) * Nk + m) * DHk + d];
#pragma unroll
        for (int rr = 0; rr < 8; rr++) acc[rr] = fmaf(pr[rr][m], vv, acc[rr]);
    }
#pragma unroll
    for (int rr = 0; rr < 8; rr++) red2[grp][rr * 64 + d] = acc[rr];
    __syncthreads();
    for (int idx = tid; idx < 512; idx += 256) {
        int rr = idx >> 6, dd = idx & 63;
        int t = tc * 8 + rr;
        if (t < NTk) {
            float s = red2[0][idx] + red2[1][idx] + red2[2][idx] + red2[3][idx];
            g_attout[((size_t)(b * NTk + t)) * Ck + h * 64 + dd] = s;
        }
    }
}

// ------------------------- host orchestration --------------------------------
extern "C" void kernel_launch(void* const* d_in, const int* in_sizes, int n_in,
                              void* d_out, int out_size) {
    const float* x      = (const float*)d_in[0];
    const float* policy = (const float*)d_in[1];
    const float* n1w    = (const float*)d_in[2];
    const float* n1b    = (const float*)d_in[3];
    const float* qkvw   = (const float*)d_in[4];
    const float* projw  = (const float*)d_in[5];
    const float* projb  = (const float*)d_in[6];
    const float* n2w    = (const float*)d_in[7];
    const float* n2b    = (const float*)d_in[8];
    const float* fc1w   = (const float*)d_in[9];
    const float* fc1b   = (const float*)d_in[10];
    const float* fc2w   = (const float*)d_in[11];
    const float* fc2b   = (const float*)d_in[12];
    float* out = (float*)d_out;

    float *p_xn, *p_attout, *p_ln2, *p_h;
    cudaGetSymbolAddress((void**)&p_xn, g_xn);
    cudaGetSymbolAddress((void**)&p_attout, g_attout);
    cudaGetSymbolAddress((void**)&p_ln2, g_ln2);
    cudaGetSymbolAddress((void**)&p_h, g_hbuf);

    const int Mqkv = Bk * Nk;   // 6280
    const int Mt   = Bk * NTk;  // 3144

    ln8_kernel<<<(Mqkv + 7) / 8, 256>>>(x, p_xn, n1w, n1b, Mqkv);

    {   // bit-exact FFMA path (feeds decisions)
        EpiQKV epi{policy};
        dim3 grid((3 * Ck + 127) / 128, (Mqkv + 127) / 128);
        gemm128<EpiQKV><<<grid, 256>>>(p_xn, qkvw, Mqkv, 3 * Ck, Ck, epi);
    }

    attn_row0_kernel<<<Bk * Hk, 256>>>();
    vnorm8_kernel<<<(Bk * Nk + 7) / 8, 256>>>();

    select_kernel<<<Bk, 1024>>>(out);

    {
        dim3 grid((NTk + 7) / 8, Hk, Bk);
        attnout_kernel<<<grid, 256>>>();
    }

    {   // continuous path: 3-split BF16 tensor cores
        EpiProj epi{x, projb, out};
        dim3 grid(Ck / 128, (Mt + 127) / 128);
        gemm_bf16s<EpiProj><<<grid, 256>>>(p_attout, projw, Mt, Ck, Ck, epi);
    }

    ln8_kernel<<<(Mt + 7) / 8, 256>>>(out, p_ln2, n2w, n2b, Mt);

    {
        EpiFc1 epi{fc1b};
        dim3 grid(FC / 128, (Mt + 127) / 128);
        gemm_bf16s<EpiFc1><<<grid, 256>>>(p_ln2, fc1w, Mt, FC, Ck, epi);
    }

    {
        EpiFc2 epi{fc2b, out};
        dim3 grid(Ck / 128, (Mt + 127) / 128);
        gemm_bf16s<EpiFc2><<<grid, 256>>>(p_h, fc2w, Mt, Ck, FC, epi);
    }
    (void)in_sizes; (void)n_in; (void)out_size;
}